// round 11
// baseline (speedup 1.0000x reference)
#include <cuda_runtime.h>
#include <cuda_fp16.h>
#include <math_constants.h>

#define N_NODES 10000
#define N_EDGES 320000
#define HID 256
#define HEADS 8
#define HDIM 32
#define MAXE 128       // per-node smem edge cache; fallback recompute beyond
#define DEG_PAD 12288  // 1024 threads * 12 per thread, int4-aligned

// GEMM tiling
#define MB 64
#define NB 64
#define KC 32
#define KPAD 36        // row pad (floats) -> conflict-free mma fragment LDS

// ---------------- scratch (no allocation allowed) ----------------
__device__ __half g_h[N_NODES * HID];    // transformed features (fp16 messages)
__device__ float g_feat[N_NODES * HID];  // layer-2 input (elu(out1)), fp32
__device__ float g_as[N_NODES * HEADS];
__device__ float g_ad[N_NODES * HEADS];
__device__ int   g_deg[DEG_PAD];
__device__ int   g_off[N_NODES + 1];
__device__ int   g_rank[N_EDGES];        // rank of edge within its dst bucket
__device__ int   g_srt[N_EDGES];         // src node id, grouped by dst (CSR)
__device__ int   g_is64;                 // 1 if edges buffer is int64, 0 if int32

// ---------------- helpers ----------------
__device__ __forceinline__ int edge_at(const void* edges, int idx) {
    if (g_is64) return (int)((const long long*)edges)[idx];
    return ((const int*)edges)[idx];
}

__device__ __forceinline__ unsigned f2tf32(float f) {
    unsigned u;
    asm("cvt.rna.tf32.f32 %0, %1;" : "=r"(u) : "f"(f));
    return u;
}

__device__ __forceinline__ void mma_tf32(
    float& c0, float& c1, float& c2, float& c3,
    unsigned a0, unsigned a1, unsigned a2, unsigned a3,
    unsigned b0, unsigned b1)
{
    asm("mma.sync.aligned.m16n8k8.row.col.f32.tf32.tf32.f32 "
        "{%0,%1,%2,%3},{%4,%5,%6,%7},{%8,%9},{%0,%1,%2,%3};"
        : "+f"(c0), "+f"(c1), "+f"(c2), "+f"(c3)
        : "r"(a0), "r"(a1), "r"(a2), "r"(a3), "r"(b0), "r"(b1));
}

// ---------------- zero + dtype detect (fused) ----------------
__global__ void zero_detect_kernel(const int* __restrict__ e32) {
    int i = blockIdx.x * blockDim.x + threadIdx.x;
    if (i < DEG_PAD) g_deg[i] = 0;
    if (i == 0) {
        int allz = 1;
        #pragma unroll
        for (int k = 1; k < 64; k += 2)
            if (e32[k] != 0) { allz = 0; break; }
        g_is64 = allz;
    }
}

// ---------------- histogram (also records per-edge rank) ----------------
__global__ void hist_kernel(const void* __restrict__ edges) {
    int e = blockIdx.x * blockDim.x + threadIdx.x;
    if (e < N_EDGES) {
        int dst = edge_at(edges, N_EDGES + e);
        int r = 0;
        if ((unsigned)dst < (unsigned)N_NODES)
            r = atomicAdd(&g_deg[dst], 1);
        g_rank[e] = r;
    }
}

// Two-level warp-shuffle scan; thread t serially scans 12 elems (3x int4 loads).
__global__ __launch_bounds__(1024) void scan_kernel() {
    __shared__ int warp_tot[32];
    const int PER = 12;
    int t    = threadIdx.x;
    int lane = t & 31, wid = t >> 5;

    int d[PER];
    #pragma unroll
    for (int q = 0; q < 3; q++) {
        int4 v4 = ((const int4*)g_deg)[t * 3 + q];
        d[q * 4 + 0] = v4.x; d[q * 4 + 1] = v4.y;
        d[q * 4 + 2] = v4.z; d[q * 4 + 3] = v4.w;
    }
    int v[PER]; int s = 0;
    #pragma unroll
    for (int i = 0; i < PER; i++) { v[i] = s; s += d[i]; }

    int x = s;
    #pragma unroll
    for (int o = 1; o < 32; o <<= 1) {
        int y = __shfl_up_sync(0xffffffffu, x, o);
        if (lane >= o) x += y;
    }
    if (lane == 31) warp_tot[wid] = x;
    __syncthreads();
    if (wid == 0) {
        int y = warp_tot[lane];
        #pragma unroll
        for (int o = 1; o < 32; o <<= 1) {
            int z = __shfl_up_sync(0xffffffffu, y, o);
            if (lane >= o) y += z;
        }
        warp_tot[lane] = y;
    }
    __syncthreads();
    int excl = x - s + (wid > 0 ? warp_tot[wid - 1] : 0);
    int base = t * PER;
    #pragma unroll
    for (int i = 0; i < PER; i++) {
        int idx = base + i;
        if (idx <= N_NODES) g_off[idx] = excl + v[i];  // padding degs are 0
    }
}

// atomic-free fill using precomputed ranks
__global__ void fill_kernel(const void* __restrict__ edges) {
    int e = blockIdx.x * blockDim.x + threadIdx.x;
    if (e < N_EDGES) {
        int src = edge_at(edges, e);
        int dst = edge_at(edges, N_EDGES + e);
        if ((unsigned)src < (unsigned)N_NODES && (unsigned)dst < (unsigned)N_NODES) {
            int pos = g_off[dst] + g_rank[e];
            if ((unsigned)pos < (unsigned)N_EDGES) g_srt[pos] = src;
        }
    }
}

// ---------------- GEMM (tf32 tensor cores): h = feat @ W + fused alphas ---------
// Block 256 thr = 8 warps; block tile 64 nodes x 64 cols; warp tile 16x32.
// Warp grid 4(m) x 2(n): warp w -> mw=(w>>1)*16, nw=(w&1)*32 (= exactly one head).
// h stored as fp16 (half2 pairs); alpha dots from fp32 accumulators.
__global__ __launch_bounds__(256) void gemm_mma_kernel(
    const float* __restrict__ x, int layer2, const float* __restrict__ W,
    const float* __restrict__ a_s, const float* __restrict__ a_d)
{
    const float* feat = layer2 ? (const float*)g_feat : x;

    __shared__ unsigned sA[MB][KPAD];   // A tile [row][k] (tf32 bits)
    __shared__ unsigned sB[NB][KPAD];   // B tile [col][k] (tf32 bits)

    int t    = threadIdx.x;
    int w    = t >> 5;
    int lane = t & 31;
    int g    = lane >> 2;     // 0..7
    int tig  = lane & 3;      // 0..3
    int m0 = blockIdx.x * MB;
    int n0 = blockIdx.y * NB;
    int mw = (w >> 1) * 16;
    int nw = (w & 1) * 32;

    float c[4][4];
    #pragma unroll
    for (int s = 0; s < 4; s++)
        #pragma unroll
        for (int i = 0; i < 4; i++) c[s][i] = 0.f;

    for (int k0 = 0; k0 < HID; k0 += KC) {
        // stage A: 64 rows x 32 k, float4 loads along k
        #pragma unroll
        for (int q = 0; q < 2; q++) {
            int lin = t + 256 * q;          // 0..511
            int row = lin >> 3;
            int kq  = (lin & 7) * 4;
            int node = m0 + row;
            float4 v = (node < N_NODES)
                ? *(const float4*)&feat[node * HID + k0 + kq]
                : make_float4(0.f, 0.f, 0.f, 0.f);
            sA[row][kq + 0] = f2tf32(v.x);
            sA[row][kq + 1] = f2tf32(v.y);
            sA[row][kq + 2] = f2tf32(v.z);
            sA[row][kq + 3] = f2tf32(v.w);
        }
        // stage B transposed: thread -> col n=t&63, k-range 8*(t>>6)..+7
        {
            int n  = t & 63;
            int q8 = (t >> 6) * 8;
            #pragma unroll
            for (int j = 0; j < 8; j++) {
                int k = q8 + j;
                sB[n][k] = f2tf32(W[(k0 + k) * HID + n0 + n]);
            }
        }
        __syncthreads();

        #pragma unroll
        for (int ks = 0; ks < KC; ks += 8) {
            unsigned a0 = sA[mw + g][ks + tig];
            unsigned a1 = sA[mw + g + 8][ks + tig];
            unsigned a2 = sA[mw + g][ks + tig + 4];
            unsigned a3 = sA[mw + g + 8][ks + tig + 4];
            #pragma unroll
            for (int s = 0; s < 4; s++) {
                unsigned b0 = sB[nw + s * 8 + g][ks + tig];
                unsigned b1 = sB[nw + s * 8 + g][ks + tig + 4];
                mma_tf32(c[s][0], c[s][1], c[s][2], c[s][3],
                         a0, a1, a2, a3, b0, b1);
            }
        }
        __syncthreads();
    }

    // Epilogue: c-reg layout: c0=(g, tig*2) c1=(g, tig*2+1) c2=(g+8, ...) c3.
    int head  = blockIdx.y * 2 + (w & 1);
    int node0 = m0 + mw + g;
    int node1 = node0 + 8;

    float2 as2[4], ad2[4];
    #pragma unroll
    for (int s = 0; s < 4; s++) {
        as2[s] = *(const float2*)&a_s[head * HDIM + s * 8 + tig * 2];
        ad2[s] = *(const float2*)&a_d[head * HDIM + s * 8 + tig * 2];
    }

    float ps0 = 0.f, pd0 = 0.f, ps1 = 0.f, pd1 = 0.f;
    #pragma unroll
    for (int s = 0; s < 4; s++) {
        int col = n0 + nw + s * 8 + tig * 2;
        if (node0 < N_NODES)
            *(__half2*)&g_h[node0 * HID + col] = __floats2half2_rn(c[s][0], c[s][1]);
        if (node1 < N_NODES)
            *(__half2*)&g_h[node1 * HID + col] = __floats2half2_rn(c[s][2], c[s][3]);
        ps0 += c[s][0] * as2[s].x + c[s][1] * as2[s].y;
        pd0 += c[s][0] * ad2[s].x + c[s][1] * ad2[s].y;
        ps1 += c[s][2] * as2[s].x + c[s][3] * as2[s].y;
        pd1 += c[s][2] * ad2[s].x + c[s][3] * ad2[s].y;
    }
    // reduce over tig (4 consecutive lanes)
    #pragma unroll
    for (int o = 2; o > 0; o >>= 1) {
        ps0 += __shfl_down_sync(0xffffffffu, ps0, o, 4);
        pd0 += __shfl_down_sync(0xffffffffu, pd0, o, 4);
        ps1 += __shfl_down_sync(0xffffffffu, ps1, o, 4);
        pd1 += __shfl_down_sync(0xffffffffu, pd1, o, 4);
    }
    if (tig == 0) {
        if (node0 < N_NODES) {
            g_as[node0 * HEADS + head] = ps0;
            g_ad[node0 * HEADS + head] = pd0;
        }
        if (node1 < N_NODES) {
            g_as[node1 * HEADS + head] = ps1;
            g_ad[node1 * HEADS + head] = pd1;
        }
    }
}

// ---------------- Aggregation: softmax over incoming edges + weighted sum ---------
// Grid: N_NODES blocks x 256 threads.
// Stage 1 (block-cooperative): thread = edge; loads src once + BOTH float4s of
// g_as[src][0..7] (2 wide loads replace 8 scattered 4B loads), computes all 8
// heads' w = exp(leakyrelu(.)), caches se[h][j] + shared ss[j]; deterministic
// two-level reduction -> per-head 1/denominator in s_inv.
// Stage 2: warp = head, quarter-warp per edge, uint2 fp16 gathers.
// mode=1: out = elu(agg + b) -> g_feat ; mode=0: out = agg + b -> d_out
__global__ __launch_bounds__(256) void agg_kernel(
    const float* __restrict__ b, float* __restrict__ out, int mode)
{
    __shared__ float se[HEADS][MAXE];   // softmax weights [head][edge]
    __shared__ int   ss[MAXE];          // src cache (shared across heads)
    __shared__ float s_adv[HEADS];
    __shared__ float warp_part[8][HEADS];
    __shared__ float s_inv[HEADS];

    int n    = blockIdx.x;
    int t    = threadIdx.x;
    int wid  = t >> 5;
    int lane = t & 31;

    int beg = g_off[n];
    int deg = g_off[n + 1] - beg;

    if (t < HEADS) s_adv[t] = g_ad[n * HEADS + t];
    __syncthreads();

    // ---- Stage 1: weights for all heads, one thread per edge ----
    float part[HEADS];
    #pragma unroll
    for (int h = 0; h < HEADS; h++) part[h] = 0.f;

    for (int j = t; j < deg; j += 256) {
        int s = g_srt[beg + j];
        float4 a0 = *(const float4*)&g_as[s * HEADS];
        float4 a1 = *(const float4*)&g_as[s * HEADS + 4];
        float av[8] = {a0.x, a0.y, a0.z, a0.w, a1.x, a1.y, a1.z, a1.w};
        if (j < MAXE) ss[j] = s;
        #pragma unroll
        for (int h = 0; h < HEADS; h++) {
            float e = av[h] + s_adv[h];
            e = (e > 0.f) ? e : 0.2f * e;
            e = fminf(fmaxf(e, -60.f), 60.f);
            float w = __expf(e);
            part[h] += w;
            if (j < MAXE) se[h][j] = w;
        }
    }
    #pragma unroll
    for (int h = 0; h < HEADS; h++) {
        float p = part[h];
        #pragma unroll
        for (int o = 16; o > 0; o >>= 1)
            p += __shfl_xor_sync(0xffffffffu, p, o);
        if (lane == 0) warp_part[wid][h] = p;
    }
    __syncthreads();
    if (t < HEADS) {
        float s = 0.f;
        #pragma unroll
        for (int w = 0; w < 8; w++) s += warp_part[w][t];
        s_inv[t] = 1.f / (s + 1e-16f);
    }
    __syncthreads();

    // ---- Stage 2: gather. Quarter-warp q handles edge j+q; lane&7 loads uint2
    // (4 fp16 channels, 8B). fp32 accumulate.
    int hd      = wid;
    int quarter = lane >> 3;  // 0..3
    int qc      = lane & 7;   // uint2 index within 32-channel head row
    float4 acc = make_float4(0.f, 0.f, 0.f, 0.f);
    for (int j = 0; j < deg; j += 4) {
        int jj = j + quarter;
        int s; float w;
        if (jj < deg) {
            if (jj < MAXE) { s = ss[jj]; w = se[hd][jj]; }
            else {
                s = g_srt[beg + jj];
                float e = g_as[s * HEADS + hd] + s_adv[hd];
                e = (e > 0.f) ? e : 0.2f * e;
                e = fminf(fmaxf(e, -60.f), 60.f);
                w = __expf(e);
            }
        } else { s = 0; w = 0.f; }
        uint2 hv = ((const uint2*)g_h)[s * (HID / 4) + hd * (HDIM / 4) + qc];
        float2 f0 = __half22float2(*(__half2*)&hv.x);
        float2 f1 = __half22float2(*(__half2*)&hv.y);
        acc.x = fmaf(f0.x, w, acc.x);
        acc.y = fmaf(f0.y, w, acc.y);
        acc.z = fmaf(f1.x, w, acc.z);
        acc.w = fmaf(f1.y, w, acc.w);
    }
    // combine quarters: lanes {qc, qc+8, qc+16, qc+24} hold same channels
    #pragma unroll
    for (int o = 8; o <= 16; o <<= 1) {
        acc.x += __shfl_xor_sync(0xffffffffu, acc.x, o);
        acc.y += __shfl_xor_sync(0xffffffffu, acc.y, o);
        acc.z += __shfl_xor_sync(0xffffffffu, acc.z, o);
        acc.w += __shfl_xor_sync(0xffffffffu, acc.w, o);
    }

    if (quarter == 0) {
        float inv = s_inv[hd];
        float4 b4 = ((const float4*)b)[hd * (HDIM / 4) + qc];
        float ox = acc.x * inv + b4.x;
        float oy = acc.y * inv + b4.y;
        float oz = acc.z * inv + b4.z;
        float ow = acc.w * inv + b4.w;
        if (mode == 1) {
            ox = (ox > 0.f) ? ox : (__expf(ox) - 1.f);
            oy = (oy > 0.f) ? oy : (__expf(oy) - 1.f);
            oz = (oz > 0.f) ? oz : (__expf(oz) - 1.f);
            ow = (ow > 0.f) ? ow : (__expf(ow) - 1.f);
            ((float4*)g_feat)[n * (HID / 4) + hd * (HDIM / 4) + qc] =
                make_float4(ox, oy, oz, ow);
        } else {
            ((float4*)out)[n * (HID / 4) + hd * (HDIM / 4) + qc] =
                make_float4(ox, oy, oz, ow);
        }
    }
}

// ---------------- launch ----------------
extern "C" void kernel_launch(void* const* d_in, const int* in_sizes, int n_in,
                              void* d_out, int out_size)
{
    const float* x     = (const float*)d_in[0];
    const void*  edges = d_in[1];                 // int32 or int64 — detected on device
    const float* W1    = (const float*)d_in[2];
    const float* as1   = (const float*)d_in[3];
    const float* ad1   = (const float*)d_in[4];
    const float* b1    = (const float*)d_in[5];
    const float* W2    = (const float*)d_in[6];
    const float* as2   = (const float*)d_in[7];
    const float* ad2   = (const float*)d_in[8];
    const float* b2    = (const float*)d_in[9];
    float* out = (float*)d_out;

    // CSR build (deterministic)
    zero_detect_kernel<<<(DEG_PAD + 255) / 256, 256>>>((const int*)edges);
    hist_kernel<<<(N_EDGES + 255) / 256, 256>>>(edges);
    scan_kernel<<<1, 1024>>>();
    fill_kernel<<<(N_EDGES + 255) / 256, 256>>>(edges);

    dim3 ggrid((N_NODES + MB - 1) / MB, HID / NB);   // (157, 4)

    // Layer 1
    gemm_mma_kernel<<<ggrid, 256>>>(x, 0, W1, as1, ad1);
    agg_kernel<<<N_NODES, 256>>>(b1, out, /*mode=*/1);

    // Layer 2
    gemm_mma_kernel<<<ggrid, 256>>>(x, 1, W2, as2, ad2);
    agg_kernel<<<N_NODES, 256>>>(b2, out, /*mode=*/0);
}

// round 12
// speedup vs baseline: 1.7076x; 1.7076x over previous
#include <cuda_runtime.h>
#include <cuda_fp16.h>
#include <math_constants.h>

#define N_NODES 10000
#define N_EDGES 320000
#define HID 256
#define HEADS 8
#define HDIM 32
#define MAXE 128       // per-(node,head) smem edge cache; fallback recompute beyond
#define DEG_PAD 12288  // 1024 threads * 12 per thread, int4-aligned

// GEMM tiling
#define MB 64
#define NB 64
#define KC 32
#define KPAD 36        // row pad (floats) -> conflict-free mma fragment LDS

// ---------------- scratch (no allocation allowed) ----------------
__device__ __half g_h[N_NODES * HID];    // transformed features (fp16 messages)
__device__ float g_feat[N_NODES * HID];  // layer-2 input (elu(out1)), fp32
__device__ float g_as[N_NODES * HEADS];
__device__ float g_ad[N_NODES * HEADS];
__device__ int   g_deg[DEG_PAD];
__device__ int   g_off[N_NODES + 1];
__device__ int   g_rank[N_EDGES];        // rank of edge within its dst bucket
__device__ int   g_srt[N_EDGES];         // src node id, grouped by dst (CSR)
__device__ int   g_is64;                 // 1 if edges buffer is int64, 0 if int32

// ---------------- helpers ----------------
__device__ __forceinline__ int edge_at(const void* edges, int idx) {
    if (g_is64) return (int)((const long long*)edges)[idx];
    return ((const int*)edges)[idx];
}

__device__ __forceinline__ unsigned f2tf32(float f) {
    unsigned u;
    asm("cvt.rna.tf32.f32 %0, %1;" : "=r"(u) : "f"(f));
    return u;
}

__device__ __forceinline__ void mma_tf32(
    float& c0, float& c1, float& c2, float& c3,
    unsigned a0, unsigned a1, unsigned a2, unsigned a3,
    unsigned b0, unsigned b1)
{
    asm("mma.sync.aligned.m16n8k8.row.col.f32.tf32.tf32.f32 "
        "{%0,%1,%2,%3},{%4,%5,%6,%7},{%8,%9},{%0,%1,%2,%3};"
        : "+f"(c0), "+f"(c1), "+f"(c2), "+f"(c3)
        : "r"(a0), "r"(a1), "r"(a2), "r"(a3), "r"(b0), "r"(b1));
}

// ---------------- zero + dtype detect (fused) ----------------
__global__ void zero_detect_kernel(const int* __restrict__ e32) {
    int i = blockIdx.x * blockDim.x + threadIdx.x;
    if (i < DEG_PAD) g_deg[i] = 0;
    if (i == 0) {
        int allz = 1;
        #pragma unroll
        for (int k = 1; k < 64; k += 2)
            if (e32[k] != 0) { allz = 0; break; }
        g_is64 = allz;
    }
}

// ---------------- histogram (also records per-edge rank) ----------------
__global__ void hist_kernel(const void* __restrict__ edges) {
    int e = blockIdx.x * blockDim.x + threadIdx.x;
    if (e < N_EDGES) {
        int dst = edge_at(edges, N_EDGES + e);
        int r = 0;
        if ((unsigned)dst < (unsigned)N_NODES)
            r = atomicAdd(&g_deg[dst], 1);
        g_rank[e] = r;
    }
}

// Two-level warp-shuffle scan; thread t serially scans 12 elems (3x int4 loads).
__global__ __launch_bounds__(1024) void scan_kernel() {
    __shared__ int warp_tot[32];
    const int PER = 12;
    int t    = threadIdx.x;
    int lane = t & 31, wid = t >> 5;

    int d[PER];
    #pragma unroll
    for (int q = 0; q < 3; q++) {
        int4 v4 = ((const int4*)g_deg)[t * 3 + q];
        d[q * 4 + 0] = v4.x; d[q * 4 + 1] = v4.y;
        d[q * 4 + 2] = v4.z; d[q * 4 + 3] = v4.w;
    }
    int v[PER]; int s = 0;
    #pragma unroll
    for (int i = 0; i < PER; i++) { v[i] = s; s += d[i]; }

    int x = s;
    #pragma unroll
    for (int o = 1; o < 32; o <<= 1) {
        int y = __shfl_up_sync(0xffffffffu, x, o);
        if (lane >= o) x += y;
    }
    if (lane == 31) warp_tot[wid] = x;
    __syncthreads();
    if (wid == 0) {
        int y = warp_tot[lane];
        #pragma unroll
        for (int o = 1; o < 32; o <<= 1) {
            int z = __shfl_up_sync(0xffffffffu, y, o);
            if (lane >= o) y += z;
        }
        warp_tot[lane] = y;
    }
    __syncthreads();
    int excl = x - s + (wid > 0 ? warp_tot[wid - 1] : 0);
    int base = t * PER;
    #pragma unroll
    for (int i = 0; i < PER; i++) {
        int idx = base + i;
        if (idx <= N_NODES) g_off[idx] = excl + v[i];  // padding degs are 0
    }
}

// atomic-free fill using precomputed ranks
__global__ void fill_kernel(const void* __restrict__ edges) {
    int e = blockIdx.x * blockDim.x + threadIdx.x;
    if (e < N_EDGES) {
        int src = edge_at(edges, e);
        int dst = edge_at(edges, N_EDGES + e);
        if ((unsigned)src < (unsigned)N_NODES && (unsigned)dst < (unsigned)N_NODES) {
            int pos = g_off[dst] + g_rank[e];
            if ((unsigned)pos < (unsigned)N_EDGES) g_srt[pos] = src;
        }
    }
}

// ---------------- GEMM (tf32 tensor cores): h = feat @ W + fused alphas ---------
// Block 256 thr = 8 warps; block tile 64 nodes x 64 cols; warp tile 16x32.
// Warp grid 4(m) x 2(n): warp w -> mw=(w>>1)*16, nw=(w&1)*32 (= exactly one head).
// h stored as fp16 (half2 pairs); alpha dots from fp32 accumulators.
__global__ __launch_bounds__(256) void gemm_mma_kernel(
    const float* __restrict__ x, int layer2, const float* __restrict__ W,
    const float* __restrict__ a_s, const float* __restrict__ a_d)
{
    const float* feat = layer2 ? (const float*)g_feat : x;

    __shared__ unsigned sA[MB][KPAD];   // A tile [row][k] (tf32 bits)
    __shared__ unsigned sB[NB][KPAD];   // B tile [col][k] (tf32 bits)

    int t    = threadIdx.x;
    int w    = t >> 5;
    int lane = t & 31;
    int g    = lane >> 2;     // 0..7
    int tig  = lane & 3;      // 0..3
    int m0 = blockIdx.x * MB;
    int n0 = blockIdx.y * NB;
    int mw = (w >> 1) * 16;
    int nw = (w & 1) * 32;

    float c[4][4];
    #pragma unroll
    for (int s = 0; s < 4; s++)
        #pragma unroll
        for (int i = 0; i < 4; i++) c[s][i] = 0.f;

    for (int k0 = 0; k0 < HID; k0 += KC) {
        // stage A: 64 rows x 32 k, float4 loads along k
        #pragma unroll
        for (int q = 0; q < 2; q++) {
            int lin = t + 256 * q;          // 0..511
            int row = lin >> 3;
            int kq  = (lin & 7) * 4;
            int node = m0 + row;
            float4 v = (node < N_NODES)
                ? *(const float4*)&feat[node * HID + k0 + kq]
                : make_float4(0.f, 0.f, 0.f, 0.f);
            sA[row][kq + 0] = f2tf32(v.x);
            sA[row][kq + 1] = f2tf32(v.y);
            sA[row][kq + 2] = f2tf32(v.z);
            sA[row][kq + 3] = f2tf32(v.w);
        }
        // stage B transposed: thread -> col n=t&63, k-range 8*(t>>6)..+7
        {
            int n  = t & 63;
            int q8 = (t >> 6) * 8;
            #pragma unroll
            for (int j = 0; j < 8; j++) {
                int k = q8 + j;
                sB[n][k] = f2tf32(W[(k0 + k) * HID + n0 + n]);
            }
        }
        __syncthreads();

        #pragma unroll
        for (int ks = 0; ks < KC; ks += 8) {
            unsigned a0 = sA[mw + g][ks + tig];
            unsigned a1 = sA[mw + g + 8][ks + tig];
            unsigned a2 = sA[mw + g][ks + tig + 4];
            unsigned a3 = sA[mw + g + 8][ks + tig + 4];
            #pragma unroll
            for (int s = 0; s < 4; s++) {
                unsigned b0 = sB[nw + s * 8 + g][ks + tig];
                unsigned b1 = sB[nw + s * 8 + g][ks + tig + 4];
                mma_tf32(c[s][0], c[s][1], c[s][2], c[s][3],
                         a0, a1, a2, a3, b0, b1);
            }
        }
        __syncthreads();
    }

    // Epilogue: c-reg layout: c0=(g, tig*2) c1=(g, tig*2+1) c2=(g+8, ...) c3.
    int head  = blockIdx.y * 2 + (w & 1);
    int node0 = m0 + mw + g;
    int node1 = node0 + 8;

    float2 as2[4], ad2[4];
    #pragma unroll
    for (int s = 0; s < 4; s++) {
        as2[s] = *(const float2*)&a_s[head * HDIM + s * 8 + tig * 2];
        ad2[s] = *(const float2*)&a_d[head * HDIM + s * 8 + tig * 2];
    }

    float ps0 = 0.f, pd0 = 0.f, ps1 = 0.f, pd1 = 0.f;
    #pragma unroll
    for (int s = 0; s < 4; s++) {
        int col = n0 + nw + s * 8 + tig * 2;
        if (node0 < N_NODES)
            *(__half2*)&g_h[node0 * HID + col] = __floats2half2_rn(c[s][0], c[s][1]);
        if (node1 < N_NODES)
            *(__half2*)&g_h[node1 * HID + col] = __floats2half2_rn(c[s][2], c[s][3]);
        ps0 += c[s][0] * as2[s].x + c[s][1] * as2[s].y;
        pd0 += c[s][0] * ad2[s].x + c[s][1] * ad2[s].y;
        ps1 += c[s][2] * as2[s].x + c[s][3] * as2[s].y;
        pd1 += c[s][2] * ad2[s].x + c[s][3] * ad2[s].y;
    }
    // reduce over tig (4 consecutive lanes)
    #pragma unroll
    for (int o = 2; o > 0; o >>= 1) {
        ps0 += __shfl_down_sync(0xffffffffu, ps0, o, 4);
        pd0 += __shfl_down_sync(0xffffffffu, pd0, o, 4);
        ps1 += __shfl_down_sync(0xffffffffu, ps1, o, 4);
        pd1 += __shfl_down_sync(0xffffffffu, pd1, o, 4);
    }
    if (tig == 0) {
        if (node0 < N_NODES) {
            g_as[node0 * HEADS + head] = ps0;
            g_ad[node0 * HEADS + head] = pd0;
        }
        if (node1 < N_NODES) {
            g_as[node1 * HEADS + head] = ps1;
            g_ad[node1 * HEADS + head] = pd1;
        }
    }
}

// ---------------- Aggregation: softmax over incoming edges + weighted sum ---------
// Grid: N_NODES blocks x 256 threads. Warp = head (8-way head parallelism across
// warps — load-bearing; do not serialize heads onto one warp).
// Weight pass: lane = edge (strided), single softmax pass (no max subtraction:
// logits provably tiny, clamped +-60).
// Gather: 8 edges/iter — quarter-warp q handles edges j+q and j+q+4, lane&7
// loads uint2 (4 fp16 channels, 8B); two independent gathers in flight.
// mode=1: out = elu(agg + b) -> g_feat ; mode=0: out = agg + b -> d_out
__global__ __launch_bounds__(256) void agg_kernel(
    const float* __restrict__ b, float* __restrict__ out, int mode)
{
    __shared__ float se[HEADS][MAXE];  // per-head softmax weight cache
    __shared__ int   ss[HEADS][MAXE];  // per-head src cache

    int n    = blockIdx.x;
    int hd   = threadIdx.x >> 5;
    int lane = threadIdx.x & 31;

    int beg = g_off[n];
    int deg = g_off[n + 1] - beg;
    float adv = g_ad[n * HEADS + hd];

    // Weight pass: w = exp(leakyrelu(as+ad)), cache w + src, reduce denominator
    float sum = 0.f;
    for (int j = lane; j < deg; j += 32) {
        int s = g_srt[beg + j];
        float e = g_as[s * HEADS + hd] + adv;
        e = (e > 0.f) ? e : 0.2f * e;
        e = fminf(fmaxf(e, -60.f), 60.f);
        float w = __expf(e);
        if (j < MAXE) { se[hd][j] = w; ss[hd][j] = s; }
        sum += w;
    }
    #pragma unroll
    for (int o = 16; o > 0; o >>= 1)
        sum += __shfl_xor_sync(0xffffffffu, sum, o);
    __syncwarp();

    // Gather: 8 edges per loop trip; quarter-warp handles 2 edges (j+q, j+q+4).
    int quarter = lane >> 3;  // 0..3
    int qc      = lane & 7;   // uint2 index within 32-channel head row
    float4 acc = make_float4(0.f, 0.f, 0.f, 0.f);
    for (int j = 0; j < deg; j += 8) {
        int j0 = j + quarter;
        int j1 = j + quarter + 4;
        int s0, s1; float w0, w1;
        if (j0 < deg) {
            if (j0 < MAXE) { s0 = ss[hd][j0]; w0 = se[hd][j0]; }
            else {
                s0 = g_srt[beg + j0];
                float e = g_as[s0 * HEADS + hd] + adv;
                e = (e > 0.f) ? e : 0.2f * e;
                e = fminf(fmaxf(e, -60.f), 60.f);
                w0 = __expf(e);
            }
        } else { s0 = 0; w0 = 0.f; }
        if (j1 < deg) {
            if (j1 < MAXE) { s1 = ss[hd][j1]; w1 = se[hd][j1]; }
            else {
                s1 = g_srt[beg + j1];
                float e = g_as[s1 * HEADS + hd] + adv;
                e = (e > 0.f) ? e : 0.2f * e;
                e = fminf(fmaxf(e, -60.f), 60.f);
                w1 = __expf(e);
            }
        } else { s1 = 0; w1 = 0.f; }
        uint2 hv0 = ((const uint2*)g_h)[s0 * (HID / 4) + hd * (HDIM / 4) + qc];
        uint2 hv1 = ((const uint2*)g_h)[s1 * (HID / 4) + hd * (HDIM / 4) + qc];
        float2 a0 = __half22float2(*(__half2*)&hv0.x);
        float2 a1 = __half22float2(*(__half2*)&hv0.y);
        float2 b0 = __half22float2(*(__half2*)&hv1.x);
        float2 b1 = __half22float2(*(__half2*)&hv1.y);
        acc.x = fmaf(a0.x, w0, fmaf(b0.x, w1, acc.x));
        acc.y = fmaf(a0.y, w0, fmaf(b0.y, w1, acc.y));
        acc.z = fmaf(a1.x, w0, fmaf(b1.x, w1, acc.z));
        acc.w = fmaf(a1.y, w0, fmaf(b1.y, w1, acc.w));
    }
    // combine quarters: lanes {qc, qc+8, qc+16, qc+24} hold same channels
    #pragma unroll
    for (int o = 8; o <= 16; o <<= 1) {
        acc.x += __shfl_xor_sync(0xffffffffu, acc.x, o);
        acc.y += __shfl_xor_sync(0xffffffffu, acc.y, o);
        acc.z += __shfl_xor_sync(0xffffffffu, acc.z, o);
        acc.w += __shfl_xor_sync(0xffffffffu, acc.w, o);
    }

    if (quarter == 0) {
        float inv = 1.f / (sum + 1e-16f);
        float4 b4 = ((const float4*)b)[hd * (HDIM / 4) + qc];
        float ox = acc.x * inv + b4.x;
        float oy = acc.y * inv + b4.y;
        float oz = acc.z * inv + b4.z;
        float ow = acc.w * inv + b4.w;
        if (mode == 1) {
            ox = (ox > 0.f) ? ox : (__expf(ox) - 1.f);
            oy = (oy > 0.f) ? oy : (__expf(oy) - 1.f);
            oz = (oz > 0.f) ? oz : (__expf(oz) - 1.f);
            ow = (ow > 0.f) ? ow : (__expf(ow) - 1.f);
            ((float4*)g_feat)[n * (HID / 4) + hd * (HDIM / 4) + qc] =
                make_float4(ox, oy, oz, ow);
        } else {
            ((float4*)out)[n * (HID / 4) + hd * (HDIM / 4) + qc] =
                make_float4(ox, oy, oz, ow);
        }
    }
}

// ---------------- launch ----------------
extern "C" void kernel_launch(void* const* d_in, const int* in_sizes, int n_in,
                              void* d_out, int out_size)
{
    const float* x     = (const float*)d_in[0];
    const void*  edges = d_in[1];                 // int32 or int64 — detected on device
    const float* W1    = (const float*)d_in[2];
    const float* as1   = (const float*)d_in[3];
    const float* ad1   = (const float*)d_in[4];
    const float* b1    = (const float*)d_in[5];
    const float* W2    = (const float*)d_in[6];
    const float* as2   = (const float*)d_in[7];
    const float* ad2   = (const float*)d_in[8];
    const float* b2    = (const float*)d_in[9];
    float* out = (float*)d_out;

    // CSR build (deterministic)
    zero_detect_kernel<<<(DEG_PAD + 255) / 256, 256>>>((const int*)edges);
    hist_kernel<<<(N_EDGES + 255) / 256, 256>>>(edges);
    scan_kernel<<<1, 1024>>>();
    fill_kernel<<<(N_EDGES + 255) / 256, 256>>>(edges);

    dim3 ggrid((N_NODES + MB - 1) / MB, HID / NB);   // (157, 4)

    // Layer 1
    gemm_mma_kernel<<<ggrid, 256>>>(x, 0, W1, as1, ad1);
    agg_kernel<<<N_NODES, 256>>>(b1, out, /*mode=*/1);

    // Layer 2
    gemm_mma_kernel<<<ggrid, 256>>>(x, 1, W2, as2, ad2);
    agg_kernel<<<N_NODES, 256>>>(b2, out, /*mode=*/0);
}

// round 13
// speedup vs baseline: 1.8627x; 1.0908x over previous
#include <cuda_runtime.h>
#include <cuda_fp16.h>
#include <math_constants.h>

#define N_NODES 10000
#define N_EDGES 320000
#define HID 256
#define HEADS 8
#define HDIM 32
#define MAXE 128       // per-node smem edge cache; fallback recompute beyond
#define SEPAD 129      // row pad for se -> conflict-free per-head broadcast LDS
#define DEG_PAD 12288  // 1024 threads * 12 per thread, int4-aligned

// GEMM tiling
#define MB 64
#define NB 64
#define KC 32
#define KPAD 36        // row pad (floats) -> conflict-free mma fragment LDS

// ---------------- scratch (no allocation allowed) ----------------
__device__ __half g_h[N_NODES * HID];    // transformed features (fp16 messages)
__device__ float g_feat[N_NODES * HID];  // layer-2 input (elu(out1)), fp32
__device__ float g_as[N_NODES * HEADS];
__device__ float g_ad[N_NODES * HEADS];
__device__ int   g_deg[DEG_PAD];
__device__ int   g_off[N_NODES + 1];
__device__ int   g_rank[N_EDGES];        // rank of edge within its dst bucket
__device__ int   g_srt[N_EDGES];         // src node id, grouped by dst (CSR)
__device__ int   g_is64;                 // 1 if edges buffer is int64, 0 if int32

// ---------------- helpers ----------------
__device__ __forceinline__ int edge_at(const void* edges, int idx) {
    if (g_is64) return (int)((const long long*)edges)[idx];
    return ((const int*)edges)[idx];
}

__device__ __forceinline__ unsigned f2tf32(float f) {
    unsigned u;
    asm("cvt.rna.tf32.f32 %0, %1;" : "=r"(u) : "f"(f));
    return u;
}

__device__ __forceinline__ void mma_tf32(
    float& c0, float& c1, float& c2, float& c3,
    unsigned a0, unsigned a1, unsigned a2, unsigned a3,
    unsigned b0, unsigned b1)
{
    asm("mma.sync.aligned.m16n8k8.row.col.f32.tf32.tf32.f32 "
        "{%0,%1,%2,%3},{%4,%5,%6,%7},{%8,%9},{%0,%1,%2,%3};"
        : "+f"(c0), "+f"(c1), "+f"(c2), "+f"(c3)
        : "r"(a0), "r"(a1), "r"(a2), "r"(a3), "r"(b0), "r"(b1));
}

__device__ __forceinline__ void acc8(float* acc, uint4 hv, float w) {
    float2 f;
    f = __half22float2(*(__half2*)&hv.x);
    acc[0] = fmaf(f.x, w, acc[0]); acc[1] = fmaf(f.y, w, acc[1]);
    f = __half22float2(*(__half2*)&hv.y);
    acc[2] = fmaf(f.x, w, acc[2]); acc[3] = fmaf(f.y, w, acc[3]);
    f = __half22float2(*(__half2*)&hv.z);
    acc[4] = fmaf(f.x, w, acc[4]); acc[5] = fmaf(f.y, w, acc[5]);
    f = __half22float2(*(__half2*)&hv.w);
    acc[6] = fmaf(f.x, w, acc[6]); acc[7] = fmaf(f.y, w, acc[7]);
}

// ---------------- zero + dtype detect (fused) ----------------
__global__ void zero_detect_kernel(const int* __restrict__ e32) {
    int i = blockIdx.x * blockDim.x + threadIdx.x;
    if (i < DEG_PAD) g_deg[i] = 0;
    if (i == 0) {
        int allz = 1;
        #pragma unroll
        for (int k = 1; k < 64; k += 2)
            if (e32[k] != 0) { allz = 0; break; }
        g_is64 = allz;
    }
}

// ---------------- histogram (also records per-edge rank) ----------------
__global__ void hist_kernel(const void* __restrict__ edges) {
    int e = blockIdx.x * blockDim.x + threadIdx.x;
    if (e < N_EDGES) {
        int dst = edge_at(edges, N_EDGES + e);
        int r = 0;
        if ((unsigned)dst < (unsigned)N_NODES)
            r = atomicAdd(&g_deg[dst], 1);
        g_rank[e] = r;
    }
}

// Two-level warp-shuffle scan; thread t serially scans 12 elems (3x int4 loads).
__global__ __launch_bounds__(1024) void scan_kernel() {
    __shared__ int warp_tot[32];
    const int PER = 12;
    int t    = threadIdx.x;
    int lane = t & 31, wid = t >> 5;

    int d[PER];
    #pragma unroll
    for (int q = 0; q < 3; q++) {
        int4 v4 = ((const int4*)g_deg)[t * 3 + q];
        d[q * 4 + 0] = v4.x; d[q * 4 + 1] = v4.y;
        d[q * 4 + 2] = v4.z; d[q * 4 + 3] = v4.w;
    }
    int v[PER]; int s = 0;
    #pragma unroll
    for (int i = 0; i < PER; i++) { v[i] = s; s += d[i]; }

    int x = s;
    #pragma unroll
    for (int o = 1; o < 32; o <<= 1) {
        int y = __shfl_up_sync(0xffffffffu, x, o);
        if (lane >= o) x += y;
    }
    if (lane == 31) warp_tot[wid] = x;
    __syncthreads();
    if (wid == 0) {
        int y = warp_tot[lane];
        #pragma unroll
        for (int o = 1; o < 32; o <<= 1) {
            int z = __shfl_up_sync(0xffffffffu, y, o);
            if (lane >= o) y += z;
        }
        warp_tot[lane] = y;
    }
    __syncthreads();
    int excl = x - s + (wid > 0 ? warp_tot[wid - 1] : 0);
    int base = t * PER;
    #pragma unroll
    for (int i = 0; i < PER; i++) {
        int idx = base + i;
        if (idx <= N_NODES) g_off[idx] = excl + v[i];  // padding degs are 0
    }
}

// atomic-free fill using precomputed ranks
__global__ void fill_kernel(const void* __restrict__ edges) {
    int e = blockIdx.x * blockDim.x + threadIdx.x;
    if (e < N_EDGES) {
        int src = edge_at(edges, e);
        int dst = edge_at(edges, N_EDGES + e);
        if ((unsigned)src < (unsigned)N_NODES && (unsigned)dst < (unsigned)N_NODES) {
            int pos = g_off[dst] + g_rank[e];
            if ((unsigned)pos < (unsigned)N_EDGES) g_srt[pos] = src;
        }
    }
}

// ---------------- GEMM (tf32 tensor cores): h = feat @ W + fused alphas ---------
// Block 256 thr = 8 warps; block tile 64 nodes x 64 cols; warp tile 16x32.
// Warp grid 4(m) x 2(n): warp w -> mw=(w>>1)*16, nw=(w&1)*32 (= exactly one head).
// h stored as fp16 (half2 pairs); alpha dots from fp32 accumulators.
__global__ __launch_bounds__(256) void gemm_mma_kernel(
    const float* __restrict__ x, int layer2, const float* __restrict__ W,
    const float* __restrict__ a_s, const float* __restrict__ a_d)
{
    const float* feat = layer2 ? (const float*)g_feat : x;

    __shared__ unsigned sA[MB][KPAD];   // A tile [row][k] (tf32 bits)
    __shared__ unsigned sB[NB][KPAD];   // B tile [col][k] (tf32 bits)

    int t    = threadIdx.x;
    int w    = t >> 5;
    int lane = t & 31;
    int g    = lane >> 2;     // 0..7
    int tig  = lane & 3;      // 0..3
    int m0 = blockIdx.x * MB;
    int n0 = blockIdx.y * NB;
    int mw = (w >> 1) * 16;
    int nw = (w & 1) * 32;

    float c[4][4];
    #pragma unroll
    for (int s = 0; s < 4; s++)
        #pragma unroll
        for (int i = 0; i < 4; i++) c[s][i] = 0.f;

    for (int k0 = 0; k0 < HID; k0 += KC) {
        // stage A: 64 rows x 32 k, float4 loads along k
        #pragma unroll
        for (int q = 0; q < 2; q++) {
            int lin = t + 256 * q;          // 0..511
            int row = lin >> 3;
            int kq  = (lin & 7) * 4;
            int node = m0 + row;
            float4 v = (node < N_NODES)
                ? *(const float4*)&feat[node * HID + k0 + kq]
                : make_float4(0.f, 0.f, 0.f, 0.f);
            sA[row][kq + 0] = f2tf32(v.x);
            sA[row][kq + 1] = f2tf32(v.y);
            sA[row][kq + 2] = f2tf32(v.z);
            sA[row][kq + 3] = f2tf32(v.w);
        }
        // stage B transposed: thread -> col n=t&63, k-range 8*(t>>6)..+7
        {
            int n  = t & 63;
            int q8 = (t >> 6) * 8;
            #pragma unroll
            for (int j = 0; j < 8; j++) {
                int k = q8 + j;
                sB[n][k] = f2tf32(W[(k0 + k) * HID + n0 + n]);
            }
        }
        __syncthreads();

        #pragma unroll
        for (int ks = 0; ks < KC; ks += 8) {
            unsigned a0 = sA[mw + g][ks + tig];
            unsigned a1 = sA[mw + g + 8][ks + tig];
            unsigned a2 = sA[mw + g][ks + tig + 4];
            unsigned a3 = sA[mw + g + 8][ks + tig + 4];
            #pragma unroll
            for (int s = 0; s < 4; s++) {
                unsigned b0 = sB[nw + s * 8 + g][ks + tig];
                unsigned b1 = sB[nw + s * 8 + g][ks + tig + 4];
                mma_tf32(c[s][0], c[s][1], c[s][2], c[s][3],
                         a0, a1, a2, a3, b0, b1);
            }
        }
        __syncthreads();
    }

    // Epilogue: c-reg layout: c0=(g, tig*2) c1=(g, tig*2+1) c2=(g+8, ...) c3.
    int head  = blockIdx.y * 2 + (w & 1);
    int node0 = m0 + mw + g;
    int node1 = node0 + 8;

    float2 as2[4], ad2[4];
    #pragma unroll
    for (int s = 0; s < 4; s++) {
        as2[s] = *(const float2*)&a_s[head * HDIM + s * 8 + tig * 2];
        ad2[s] = *(const float2*)&a_d[head * HDIM + s * 8 + tig * 2];
    }

    float ps0 = 0.f, pd0 = 0.f, ps1 = 0.f, pd1 = 0.f;
    #pragma unroll
    for (int s = 0; s < 4; s++) {
        int col = n0 + nw + s * 8 + tig * 2;
        if (node0 < N_NODES)
            *(__half2*)&g_h[node0 * HID + col] = __floats2half2_rn(c[s][0], c[s][1]);
        if (node1 < N_NODES)
            *(__half2*)&g_h[node1 * HID + col] = __floats2half2_rn(c[s][2], c[s][3]);
        ps0 += c[s][0] * as2[s].x + c[s][1] * as2[s].y;
        pd0 += c[s][0] * ad2[s].x + c[s][1] * ad2[s].y;
        ps1 += c[s][2] * as2[s].x + c[s][3] * as2[s].y;
        pd1 += c[s][2] * ad2[s].x + c[s][3] * ad2[s].y;
    }
    // reduce over tig (4 consecutive lanes)
    #pragma unroll
    for (int o = 2; o > 0; o >>= 1) {
        ps0 += __shfl_down_sync(0xffffffffu, ps0, o, 4);
        pd0 += __shfl_down_sync(0xffffffffu, pd0, o, 4);
        ps1 += __shfl_down_sync(0xffffffffu, ps1, o, 4);
        pd1 += __shfl_down_sync(0xffffffffu, pd1, o, 4);
    }
    if (tig == 0) {
        if (node0 < N_NODES) {
            g_as[node0 * HEADS + head] = ps0;
            g_ad[node0 * HEADS + head] = pd0;
        }
        if (node1 < N_NODES) {
            g_as[node1 * HEADS + head] = ps1;
            g_ad[node1 * HEADS + head] = pd1;
        }
    }
}

// ---------------- Aggregation: softmax over incoming edges + weighted sum ---------
// Grid: N_NODES blocks x 256 threads.
// Weight pass (proven): warp = head, lane = edge, single softmax pass.
// Gather (NEW): warp = edge (warps round-robin j mod 8, 2 edges in flight/trip);
//   lane loads uint4 = 8 fp16 channels -> whole 512B h[src] row in ONE coalesced
//   access serving all 8 heads; per-edge weight via broadcast LDS from the
//   row-padded weight cache. Deterministic 8-partial block reduction at the end.
// mode=1: out = elu(agg + b) -> g_feat ; mode=0: out = agg + b -> d_out
__global__ __launch_bounds__(256) void agg_kernel(
    const float* __restrict__ b, float* __restrict__ out, int mode)
{
    __shared__ float se[HEADS][SEPAD];  // softmax weights, row-padded
    __shared__ int   ss[MAXE];          // src cache (single copy)
    __shared__ float s_adv[HEADS];
    __shared__ float s_inv[HEADS];
    __shared__ float red[8][HID];       // per-warp channel partials (8 KB)

    int n    = blockIdx.x;
    int t    = threadIdx.x;
    int hd   = t >> 5;
    int lane = t & 31;

    int beg = g_off[n];
    int deg = g_off[n + 1] - beg;
    float adv = g_ad[n * HEADS + hd];
    if (lane == 0) s_adv[hd] = adv;

    // ---- Weight pass: warp = head, lane = edge ----
    float sum = 0.f;
    for (int j = lane; j < deg; j += 32) {
        int s = g_srt[beg + j];
        float e = g_as[s * HEADS + hd] + adv;
        e = (e > 0.f) ? e : 0.2f * e;
        e = fminf(fmaxf(e, -60.f), 60.f);
        float w = __expf(e);
        if (j < MAXE) { se[hd][j] = w; if (hd == 0) ss[j] = s; }
        sum += w;
    }
    #pragma unroll
    for (int o = 16; o > 0; o >>= 1)
        sum += __shfl_xor_sync(0xffffffffu, sum, o);
    if (lane == 0) s_inv[hd] = 1.f / (sum + 1e-16f);
    __syncthreads();

    // ---- Gather: warp = edge; 2 edges per trip (j, j+8) ----
    int hgrp = lane >> 2;               // head owning this lane's 8 channels
    float acc[8];
    #pragma unroll
    for (int i = 0; i < 8; i++) acc[i] = 0.f;

    for (int j = hd; j < deg; j += 16) {
        int ja = j, jb = j + 8;
        int sa; float wa;
        if (ja < MAXE) { sa = ss[ja]; wa = se[hgrp][ja]; }
        else {
            sa = g_srt[beg + ja];
            float e = g_as[sa * HEADS + hgrp] + s_adv[hgrp];
            e = (e > 0.f) ? e : 0.2f * e;
            e = fminf(fmaxf(e, -60.f), 60.f);
            wa = __expf(e);
        }
        int sb = 0; float wb = 0.f;
        if (jb < deg) {
            if (jb < MAXE) { sb = ss[jb]; wb = se[hgrp][jb]; }
            else {
                sb = g_srt[beg + jb];
                float e = g_as[sb * HEADS + hgrp] + s_adv[hgrp];
                e = (e > 0.f) ? e : 0.2f * e;
                e = fminf(fmaxf(e, -60.f), 60.f);
                wb = __expf(e);
            }
        }
        uint4 ha = ((const uint4*)g_h)[sa * (HID / 8) + lane];
        uint4 hb = ((const uint4*)g_h)[sb * (HID / 8) + lane];
        acc8(acc, ha, wa);
        acc8(acc, hb, wb);
    }

    // write per-warp partials: lane owns channels lane*8..+7
    *(float4*)&red[hd][lane * 8]     = make_float4(acc[0], acc[1], acc[2], acc[3]);
    *(float4*)&red[hd][lane * 8 + 4] = make_float4(acc[4], acc[5], acc[6], acc[7]);
    __syncthreads();

    // ---- Final: thread t = channel t; fixed-order sum over 8 warps ----
    float s = 0.f;
    #pragma unroll
    for (int w8 = 0; w8 < 8; w8++) s += red[w8][t];
    int ch_head = t >> 5;
    float o = s * s_inv[ch_head] + b[t];
    if (mode == 1) {
        o = (o > 0.f) ? o : (__expf(o) - 1.f);
        g_feat[n * HID + t] = o;
    } else {
        out[n * HID + t] = o;
    }
}

// ---------------- launch ----------------
extern "C" void kernel_launch(void* const* d_in, const int* in_sizes, int n_in,
                              void* d_out, int out_size)
{
    const float* x     = (const float*)d_in[0];
    const void*  edges = d_in[1];                 // int32 or int64 — detected on device
    const float* W1    = (const float*)d_in[2];
    const float* as1   = (const float*)d_in[3];
    const float* ad1   = (const float*)d_in[4];
    const float* b1    = (const float*)d_in[5];
    const float* W2    = (const float*)d_in[6];
    const float* as2   = (const float*)d_in[7];
    const float* ad2   = (const float*)d_in[8];
    const float* b2    = (const float*)d_in[9];
    float* out = (float*)d_out;

    // CSR build (deterministic)
    zero_detect_kernel<<<(DEG_PAD + 255) / 256, 256>>>((const int*)edges);
    hist_kernel<<<(N_EDGES + 255) / 256, 256>>>(edges);
    scan_kernel<<<1, 1024>>>();
    fill_kernel<<<(N_EDGES + 255) / 256, 256>>>(edges);

    dim3 ggrid((N_NODES + MB - 1) / MB, HID / NB);   // (157, 4)

    // Layer 1
    gemm_mma_kernel<<<ggrid, 256>>>(x, 0, W1, as1, ad1);
    agg_kernel<<<N_NODES, 256>>>(b1, out, /*mode=*/1);

    // Layer 2
    gemm_mma_kernel<<<ggrid, 256>>>(x, 1, W2, as2, ad2);
    agg_kernel<<<N_NODES, 256>>>(b2, out, /*mode=*/0);
}

// round 15
// speedup vs baseline: 2.0834x; 1.1185x over previous
#include <cuda_runtime.h>
#include <cuda_fp16.h>
#include <math_constants.h>

#define N_NODES 10000
#define N_EDGES 320000
#define HID 256
#define HEADS 8
#define HDIM 32
#define DEG_PAD 12288  // 1024 threads * 12 per thread, int4-aligned

// GEMM tiling
#define MB 64
#define NB 64
#define KC 32
#define KPAD 36        // row pad (floats) -> conflict-free mma fragment LDS

// ---------------- scratch (no allocation allowed) ----------------
__device__ __half g_h[N_NODES * HID];    // transformed features (fp16 messages)
__device__ float g_feat[N_NODES * HID];  // layer-2 input (elu(out1)), fp32
__device__ float g_as[N_NODES * HEADS];
__device__ float g_ad[N_NODES * HEADS];
__device__ int   g_deg[DEG_PAD];
__device__ int   g_off[N_NODES + 1];
__device__ int   g_rank[N_EDGES];        // rank of edge within its dst bucket
__device__ int   g_srt[N_EDGES];         // src node id, grouped by dst (CSR)
__device__ int   g_is64;                 // 1 if edges buffer is int64, 0 if int32

// ---------------- helpers ----------------
__device__ __forceinline__ int edge_at(const void* edges, int idx) {
    if (g_is64) return (int)((const long long*)edges)[idx];
    return ((const int*)edges)[idx];
}

__device__ __forceinline__ unsigned f2tf32(float f) {
    unsigned u;
    asm("cvt.rna.tf32.f32 %0, %1;" : "=r"(u) : "f"(f));
    return u;
}

__device__ __forceinline__ void mma_tf32(
    float& c0, float& c1, float& c2, float& c3,
    unsigned a0, unsigned a1, unsigned a2, unsigned a3,
    unsigned b0, unsigned b1)
{
    asm("mma.sync.aligned.m16n8k8.row.col.f32.tf32.tf32.f32 "
        "{%0,%1,%2,%3},{%4,%5,%6,%7},{%8,%9},{%0,%1,%2,%3};"
        : "+f"(c0), "+f"(c1), "+f"(c2), "+f"(c3)
        : "r"(a0), "r"(a1), "r"(a2), "r"(a3), "r"(b0), "r"(b1));
}

__device__ __forceinline__ void acc8(float* acc, uint4 hv, float w) {
    float2 f;
    f = __half22float2(*(__half2*)&hv.x);
    acc[0] = fmaf(f.x, w, acc[0]); acc[1] = fmaf(f.y, w, acc[1]);
    f = __half22float2(*(__half2*)&hv.y);
    acc[2] = fmaf(f.x, w, acc[2]); acc[3] = fmaf(f.y, w, acc[3]);
    f = __half22float2(*(__half2*)&hv.z);
    acc[4] = fmaf(f.x, w, acc[4]); acc[5] = fmaf(f.y, w, acc[5]);
    f = __half22float2(*(__half2*)&hv.w);
    acc[6] = fmaf(f.x, w, acc[6]); acc[7] = fmaf(f.y, w, acc[7]);
}

// ---------------- zero + dtype detect (fused) ----------------
__global__ void zero_detect_kernel(const int* __restrict__ e32) {
    int i = blockIdx.x * blockDim.x + threadIdx.x;
    if (i < DEG_PAD) g_deg[i] = 0;
    if (i == 0) {
        int allz = 1;
        #pragma unroll
        for (int k = 1; k < 64; k += 2)
            if (e32[k] != 0) { allz = 0; break; }
        g_is64 = allz;
    }
}

// ---------------- histogram (also records per-edge rank) ----------------
__global__ void hist_kernel(const void* __restrict__ edges) {
    int e = blockIdx.x * blockDim.x + threadIdx.x;
    if (e < N_EDGES) {
        int dst = edge_at(edges, N_EDGES + e);
        int r = 0;
        if ((unsigned)dst < (unsigned)N_NODES)
            r = atomicAdd(&g_deg[dst], 1);
        g_rank[e] = r;
    }
}

// Two-level warp-shuffle scan; thread t serially scans 12 elems (3x int4 loads).
__global__ __launch_bounds__(1024) void scan_kernel() {
    __shared__ int warp_tot[32];
    const int PER = 12;
    int t    = threadIdx.x;
    int lane = t & 31, wid = t >> 5;

    int d[PER];
    #pragma unroll
    for (int q = 0; q < 3; q++) {
        int4 v4 = ((const int4*)g_deg)[t * 3 + q];
        d[q * 4 + 0] = v4.x; d[q * 4 + 1] = v4.y;
        d[q * 4 + 2] = v4.z; d[q * 4 + 3] = v4.w;
    }
    int v[PER]; int s = 0;
    #pragma unroll
    for (int i = 0; i < PER; i++) { v[i] = s; s += d[i]; }

    int x = s;
    #pragma unroll
    for (int o = 1; o < 32; o <<= 1) {
        int y = __shfl_up_sync(0xffffffffu, x, o);
        if (lane >= o) x += y;
    }
    if (lane == 31) warp_tot[wid] = x;
    __syncthreads();
    if (wid == 0) {
        int y = warp_tot[lane];
        #pragma unroll
        for (int o = 1; o < 32; o <<= 1) {
            int z = __shfl_up_sync(0xffffffffu, y, o);
            if (lane >= o) y += z;
        }
        warp_tot[lane] = y;
    }
    __syncthreads();
    int excl = x - s + (wid > 0 ? warp_tot[wid - 1] : 0);
    int base = t * PER;
    #pragma unroll
    for (int i = 0; i < PER; i++) {
        int idx = base + i;
        if (idx <= N_NODES) g_off[idx] = excl + v[i];  // padding degs are 0
    }
}

// atomic-free fill using precomputed ranks
__global__ void fill_kernel(const void* __restrict__ edges) {
    int e = blockIdx.x * blockDim.x + threadIdx.x;
    if (e < N_EDGES) {
        int src = edge_at(edges, e);
        int dst = edge_at(edges, N_EDGES + e);
        if ((unsigned)src < (unsigned)N_NODES && (unsigned)dst < (unsigned)N_NODES) {
            int pos = g_off[dst] + g_rank[e];
            if ((unsigned)pos < (unsigned)N_EDGES) g_srt[pos] = src;
        }
    }
}

// ---------------- GEMM (tf32 tensor cores): h = feat @ W + fused alphas ---------
// Block 256 thr = 8 warps; block tile 64 nodes x 64 cols; warp tile 16x32.
// Warp grid 4(m) x 2(n): warp w -> mw=(w>>1)*16, nw=(w&1)*32 (= exactly one head).
// h stored as fp16 (half2 pairs); alpha dots from fp32 accumulators.
__global__ __launch_bounds__(256) void gemm_mma_kernel(
    const float* __restrict__ x, int layer2, const float* __restrict__ W,
    const float* __restrict__ a_s, const float* __restrict__ a_d)
{
    const float* feat = layer2 ? (const float*)g_feat : x;

    __shared__ unsigned sA[MB][KPAD];   // A tile [row][k] (tf32 bits)
    __shared__ unsigned sB[NB][KPAD];   // B tile [col][k] (tf32 bits)

    int t    = threadIdx.x;
    int w    = t >> 5;
    int lane = t & 31;
    int g    = lane >> 2;     // 0..7
    int tig  = lane & 3;      // 0..3
    int m0 = blockIdx.x * MB;
    int n0 = blockIdx.y * NB;
    int mw = (w >> 1) * 16;
    int nw = (w & 1) * 32;

    float c[4][4];
    #pragma unroll
    for (int s = 0; s < 4; s++)
        #pragma unroll
        for (int i = 0; i < 4; i++) c[s][i] = 0.f;

    for (int k0 = 0; k0 < HID; k0 += KC) {
        // stage A: 64 rows x 32 k, float4 loads along k
        #pragma unroll
        for (int q = 0; q < 2; q++) {
            int lin = t + 256 * q;          // 0..511
            int row = lin >> 3;
            int kq  = (lin & 7) * 4;
            int node = m0 + row;
            float4 v = (node < N_NODES)
                ? *(const float4*)&feat[node * HID + k0 + kq]
                : make_float4(0.f, 0.f, 0.f, 0.f);
            sA[row][kq + 0] = f2tf32(v.x);
            sA[row][kq + 1] = f2tf32(v.y);
            sA[row][kq + 2] = f2tf32(v.z);
            sA[row][kq + 3] = f2tf32(v.w);
        }
        // stage B transposed: thread -> col n=t&63, k-range 8*(t>>6)..+7
        {
            int n  = t & 63;
            int q8 = (t >> 6) * 8;
            #pragma unroll
            for (int j = 0; j < 8; j++) {
                int k = q8 + j;
                sB[n][k] = f2tf32(W[(k0 + k) * HID + n0 + n]);
            }
        }
        __syncthreads();

        #pragma unroll
        for (int ks = 0; ks < KC; ks += 8) {
            unsigned a0 = sA[mw + g][ks + tig];
            unsigned a1 = sA[mw + g + 8][ks + tig];
            unsigned a2 = sA[mw + g][ks + tig + 4];
            unsigned a3 = sA[mw + g + 8][ks + tig + 4];
            #pragma unroll
            for (int s = 0; s < 4; s++) {
                unsigned b0 = sB[nw + s * 8 + g][ks + tig];
                unsigned b1 = sB[nw + s * 8 + g][ks + tig + 4];
                mma_tf32(c[s][0], c[s][1], c[s][2], c[s][3],
                         a0, a1, a2, a3, b0, b1);
            }
        }
        __syncthreads();
    }

    // Epilogue: c-reg layout: c0=(g, tig*2) c1=(g, tig*2+1) c2=(g+8, ...) c3.
    int head  = blockIdx.y * 2 + (w & 1);
    int node0 = m0 + mw + g;
    int node1 = node0 + 8;

    float2 as2[4], ad2[4];
    #pragma unroll
    for (int s = 0; s < 4; s++) {
        as2[s] = *(const float2*)&a_s[head * HDIM + s * 8 + tig * 2];
        ad2[s] = *(const float2*)&a_d[head * HDIM + s * 8 + tig * 2];
    }

    float ps0 = 0.f, pd0 = 0.f, ps1 = 0.f, pd1 = 0.f;
    #pragma unroll
    for (int s = 0; s < 4; s++) {
        int col = n0 + nw + s * 8 + tig * 2;
        if (node0 < N_NODES)
            *(__half2*)&g_h[node0 * HID + col] = __floats2half2_rn(c[s][0], c[s][1]);
        if (node1 < N_NODES)
            *(__half2*)&g_h[node1 * HID + col] = __floats2half2_rn(c[s][2], c[s][3]);
        ps0 += c[s][0] * as2[s].x + c[s][1] * as2[s].y;
        pd0 += c[s][0] * ad2[s].x + c[s][1] * ad2[s].y;
        ps1 += c[s][2] * as2[s].x + c[s][3] * as2[s].y;
        pd1 += c[s][2] * ad2[s].x + c[s][3] * ad2[s].y;
    }
    // reduce over tig (4 consecutive lanes)
    #pragma unroll
    for (int o = 2; o > 0; o >>= 1) {
        ps0 += __shfl_down_sync(0xffffffffu, ps0, o, 4);
        pd0 += __shfl_down_sync(0xffffffffu, pd0, o, 4);
        ps1 += __shfl_down_sync(0xffffffffu, ps1, o, 4);
        pd1 += __shfl_down_sync(0xffffffffu, pd1, o, 4);
    }
    if (tig == 0) {
        if (node0 < N_NODES) {
            g_as[node0 * HEADS + head] = ps0;
            g_ad[node0 * HEADS + head] = pd0;
        }
        if (node1 < N_NODES) {
            g_as[node1 * HEADS + head] = ps1;
            g_ad[node1 * HEADS + head] = pd1;
        }
    }
}

// ---------------- Aggregation: single-pass softmax + weighted sum ----------------
// Grid: N_NODES blocks x 256 threads. Warp = edge (round-robin j mod 8, 2 edges
// in flight per trip). Per edge: one broadcast g_srt load; lanes read the 32B
// g_as row (lane's head = lane>>2) and compute w = exp(leakyrelu(.)) inline
// (MUFU cost is per warp-instruction, lane redundancy is free); lane gathers
// uint4 = 8 fp16 channels of its head. Denominator accumulated in the same loop
// via predicated add on one lane per head-group; fixed-order cross-warp combine
// (deterministic). No weight cache, no MAXE fallback, single __syncthreads pair.
// mode=1: out = elu(agg + b) -> g_feat ; mode=0: out = agg + b -> d_out
__global__ __launch_bounds__(256) void agg_kernel(
    const float* __restrict__ b, float* __restrict__ out, int mode)
{
    __shared__ float red[8][HID];       // per-warp channel partials (8 KB)
    __shared__ float dpart[8][HEADS];   // per-warp per-head denominator partials
    __shared__ float s_inv[HEADS];

    int n    = blockIdx.x;
    int t    = threadIdx.x;
    int wid  = t >> 5;
    int lane = t & 31;
    int hgrp = lane >> 2;               // head owning this lane's 8 channels

    int beg = g_off[n];
    int deg = g_off[n + 1] - beg;
    float adv = g_ad[n * HEADS + hgrp];             // 32B sector, broadcast-ish
    bool dlead = (lane & 3) == 0;

    float acc[8];
    #pragma unroll
    for (int i = 0; i < 8; i++) acc[i] = 0.f;
    float dsum = 0.f;

    for (int j = wid; j < deg; j += 16) {
        int jb = j + 8;
        // edge A
        int sa = g_srt[beg + j];                    // warp-uniform broadcast
        float ea = g_as[sa * HEADS + hgrp] + adv;   // one 32B sector
        ea = (ea > 0.f) ? ea : 0.2f * ea;
        ea = fminf(fmaxf(ea, -60.f), 60.f);
        float wa = __expf(ea);
        uint4 ha = ((const uint4*)g_h)[sa * (HID / 8) + lane];
        if (dlead) dsum += wa;
        acc8(acc, ha, wa);
        // edge B (warp-uniform guard)
        if (jb < deg) {
            int sb = g_srt[beg + jb];
            float eb = g_as[sb * HEADS + hgrp] + adv;
            eb = (eb > 0.f) ? eb : 0.2f * eb;
            eb = fminf(fmaxf(eb, -60.f), 60.f);
            float wb = __expf(eb);
            uint4 hb = ((const uint4*)g_h)[sb * (HID / 8) + lane];
            if (dlead) dsum += wb;
            acc8(acc, hb, wb);
        }
    }

    if (dlead) dpart[wid][hgrp] = dsum;
    *(float4*)&red[wid][lane * 8]     = make_float4(acc[0], acc[1], acc[2], acc[3]);
    *(float4*)&red[wid][lane * 8 + 4] = make_float4(acc[4], acc[5], acc[6], acc[7]);
    __syncthreads();

    if (t < HEADS) {
        float s = 0.f;
        #pragma unroll
        for (int w8 = 0; w8 < 8; w8++) s += dpart[w8][t];
        s_inv[t] = 1.f / (s + 1e-16f);
    }
    __syncthreads();

    // thread t = channel t; fixed-order sum over 8 warps
    float s = 0.f;
    #pragma unroll
    for (int w8 = 0; w8 < 8; w8++) s += red[w8][t];
    float o = s * s_inv[t >> 5] + b[t];
    if (mode == 1) {
        o = (o > 0.f) ? o : (__expf(o) - 1.f);
        g_feat[n * HID + t] = o;
    } else {
        out[n * HID + t] = o;
    }
}

// ---------------- launch ----------------
extern "C" void kernel_launch(void* const* d_in, const int* in_sizes, int n_in,
                              void* d_out, int out_size)
{
    const float* x     = (const float*)d_in[0];
    const void*  edges = d_in[1];                 // int32 or int64 — detected on device
    const float* W1    = (const float*)d_in[2];
    const float* as1   = (const float*)d_in[3];
    const float* ad1   = (const float*)d_in[4];
    const float* b1    = (const float*)d_in[5];
    const float* W2    = (const float*)d_in[6];
    const float* as2   = (const float*)d_in[7];
    const float* ad2   = (const float*)d_in[8];
    const float* b2    = (const float*)d_in[9];
    float* out = (float*)d_out;

    // CSR build (deterministic)
    zero_detect_kernel<<<(DEG_PAD + 255) / 256, 256>>>((const int*)edges);
    hist_kernel<<<(N_EDGES + 255) / 256, 256>>>(edges);
    scan_kernel<<<1, 1024>>>();
    fill_kernel<<<(N_EDGES + 255) / 256, 256>>>(edges);

    dim3 ggrid((N_NODES + MB - 1) / MB, HID / NB);   // (157, 4)

    // Layer 1
    gemm_mma_kernel<<<ggrid, 256>>>(x, 0, W1, as1, ad1);
    agg_kernel<<<N_NODES, 256>>>(b1, out, /*mode=*/1);

    // Layer 2
    gemm_mma_kernel<<<ggrid, 256>>>(x, 1, W2, as2, ad2);
    agg_kernel<<<N_NODES, 256>>>(b2, out, /*mode=*/0);
}

// round 16
// speedup vs baseline: 2.3697x; 1.1375x over previous
#include <cuda_runtime.h>
#include <cuda_fp16.h>
#include <math_constants.h>

#define N_NODES 10000
#define N_EDGES 320000
#define HID 256
#define HEADS 8
#define HDIM 32
#define DEG_PAD 12288  // 1024 threads * 12 per thread, int4-aligned

// GEMM tiling
#define MB 64
#define NB 64
#define KC 32
#define KPAD 36        // row pad (floats) -> conflict-free mma fragment LDS

// ---------------- scratch (no allocation allowed) ----------------
__device__ __half g_h[N_NODES * HID];    // transformed features (fp16 messages)
__device__ float g_feat[N_NODES * HID];  // layer-2 input (elu(out1)), fp32
__device__ float g_as[N_NODES * HEADS];
__device__ float g_ad[N_NODES * HEADS];
__device__ int   g_deg[DEG_PAD];
__device__ int   g_off[N_NODES + 1];
__device__ int   g_rank[N_EDGES];        // rank of edge within its dst bucket
__device__ int   g_srt[N_EDGES];         // src node id, grouped by dst (CSR)
__device__ int   g_is64;                 // 1 if edges buffer is int64, 0 if int32

// ---------------- helpers ----------------
__device__ __forceinline__ int edge_at(const void* edges, int idx) {
    if (g_is64) return (int)((const long long*)edges)[idx];
    return ((const int*)edges)[idx];
}

__device__ __forceinline__ unsigned f2tf32(float f) {
    unsigned u;
    asm("cvt.rna.tf32.f32 %0, %1;" : "=r"(u) : "f"(f));
    return u;
}

__device__ __forceinline__ void mma_tf32(
    float& c0, float& c1, float& c2, float& c3,
    unsigned a0, unsigned a1, unsigned a2, unsigned a3,
    unsigned b0, unsigned b1)
{
    asm("mma.sync.aligned.m16n8k8.row.col.f32.tf32.tf32.f32 "
        "{%0,%1,%2,%3},{%4,%5,%6,%7},{%8,%9},{%0,%1,%2,%3};"
        : "+f"(c0), "+f"(c1), "+f"(c2), "+f"(c3)
        : "r"(a0), "r"(a1), "r"(a2), "r"(a3), "r"(b0), "r"(b1));
}

__device__ __forceinline__ void acc8(float* acc, uint4 hv, float w) {
    float2 f;
    f = __half22float2(*(__half2*)&hv.x);
    acc[0] = fmaf(f.x, w, acc[0]); acc[1] = fmaf(f.y, w, acc[1]);
    f = __half22float2(*(__half2*)&hv.y);
    acc[2] = fmaf(f.x, w, acc[2]); acc[3] = fmaf(f.y, w, acc[3]);
    f = __half22float2(*(__half2*)&hv.z);
    acc[4] = fmaf(f.x, w, acc[4]); acc[5] = fmaf(f.y, w, acc[5]);
    f = __half22float2(*(__half2*)&hv.w);
    acc[6] = fmaf(f.x, w, acc[6]); acc[7] = fmaf(f.y, w, acc[7]);
}

// ---------------- zero + dtype detect (fused) ----------------
__global__ void zero_detect_kernel(const int* __restrict__ e32) {
    int i = blockIdx.x * blockDim.x + threadIdx.x;
    if (i < DEG_PAD) g_deg[i] = 0;
    if (i == 0) {
        int allz = 1;
        #pragma unroll
        for (int k = 1; k < 64; k += 2)
            if (e32[k] != 0) { allz = 0; break; }
        g_is64 = allz;
    }
}

// ---------------- histogram: 4 edges per thread (MLP) ----------------
__global__ void hist_kernel(const void* __restrict__ edges) {
    int e0 = (blockIdx.x * blockDim.x + threadIdx.x) * 4;
    #pragma unroll
    for (int k = 0; k < 4; k++) {
        int e = e0 + k;
        if (e < N_EDGES) {
            int dst = edge_at(edges, N_EDGES + e);
            int r = 0;
            if ((unsigned)dst < (unsigned)N_NODES)
                r = atomicAdd(&g_deg[dst], 1);
            g_rank[e] = r;
        }
    }
}

// Two-level warp-shuffle scan; thread t serially scans 12 elems (3x int4 loads).
__global__ __launch_bounds__(1024) void scan_kernel() {
    __shared__ int warp_tot[32];
    const int PER = 12;
    int t    = threadIdx.x;
    int lane = t & 31, wid = t >> 5;

    int d[PER];
    #pragma unroll
    for (int q = 0; q < 3; q++) {
        int4 v4 = ((const int4*)g_deg)[t * 3 + q];
        d[q * 4 + 0] = v4.x; d[q * 4 + 1] = v4.y;
        d[q * 4 + 2] = v4.z; d[q * 4 + 3] = v4.w;
    }
    int v[PER]; int s = 0;
    #pragma unroll
    for (int i = 0; i < PER; i++) { v[i] = s; s += d[i]; }

    int x = s;
    #pragma unroll
    for (int o = 1; o < 32; o <<= 1) {
        int y = __shfl_up_sync(0xffffffffu, x, o);
        if (lane >= o) x += y;
    }
    if (lane == 31) warp_tot[wid] = x;
    __syncthreads();
    if (wid == 0) {
        int y = warp_tot[lane];
        #pragma unroll
        for (int o = 1; o < 32; o <<= 1) {
            int z = __shfl_up_sync(0xffffffffu, y, o);
            if (lane >= o) y += z;
        }
        warp_tot[lane] = y;
    }
    __syncthreads();
    int excl = x - s + (wid > 0 ? warp_tot[wid - 1] : 0);
    int base = t * PER;
    #pragma unroll
    for (int i = 0; i < PER; i++) {
        int idx = base + i;
        if (idx <= N_NODES) g_off[idx] = excl + v[i];  // padding degs are 0
    }
}

// atomic-free fill (precomputed ranks), 4 edges per thread (MLP)
__global__ void fill_kernel(const void* __restrict__ edges) {
    int e0 = (blockIdx.x * blockDim.x + threadIdx.x) * 4;
    #pragma unroll
    for (int k = 0; k < 4; k++) {
        int e = e0 + k;
        if (e < N_EDGES) {
            int src = edge_at(edges, e);
            int dst = edge_at(edges, N_EDGES + e);
            if ((unsigned)src < (unsigned)N_NODES && (unsigned)dst < (unsigned)N_NODES) {
                int pos = g_off[dst] + g_rank[e];
                if ((unsigned)pos < (unsigned)N_EDGES) g_srt[pos] = src;
            }
        }
    }
}

// ---------------- GEMM (tf32 tensor cores): h = feat @ W + fused alphas ---------
// Block 256 thr = 8 warps; block tile 64 nodes x 64 cols; warp tile 16x32.
// Warp grid 4(m) x 2(n): warp w -> mw=(w>>1)*16, nw=(w&1)*32 (= exactly one head).
// h stored as fp16 (half2 pairs); alpha dots from fp32 accumulators.
__global__ __launch_bounds__(256) void gemm_mma_kernel(
    const float* __restrict__ x, int layer2, const float* __restrict__ W,
    const float* __restrict__ a_s, const float* __restrict__ a_d)
{
    const float* feat = layer2 ? (const float*)g_feat : x;

    __shared__ unsigned sA[MB][KPAD];   // A tile [row][k] (tf32 bits)
    __shared__ unsigned sB[NB][KPAD];   // B tile [col][k] (tf32 bits)

    int t    = threadIdx.x;
    int w    = t >> 5;
    int lane = t & 31;
    int g    = lane >> 2;     // 0..7
    int tig  = lane & 3;      // 0..3
    int m0 = blockIdx.x * MB;
    int n0 = blockIdx.y * NB;
    int mw = (w >> 1) * 16;
    int nw = (w & 1) * 32;

    float c[4][4];
    #pragma unroll
    for (int s = 0; s < 4; s++)
        #pragma unroll
        for (int i = 0; i < 4; i++) c[s][i] = 0.f;

    for (int k0 = 0; k0 < HID; k0 += KC) {
        // stage A: 64 rows x 32 k, float4 loads along k
        #pragma unroll
        for (int q = 0; q < 2; q++) {
            int lin = t + 256 * q;          // 0..511
            int row = lin >> 3;
            int kq  = (lin & 7) * 4;
            int node = m0 + row;
            float4 v = (node < N_NODES)
                ? *(const float4*)&feat[node * HID + k0 + kq]
                : make_float4(0.f, 0.f, 0.f, 0.f);
            sA[row][kq + 0] = f2tf32(v.x);
            sA[row][kq + 1] = f2tf32(v.y);
            sA[row][kq + 2] = f2tf32(v.z);
            sA[row][kq + 3] = f2tf32(v.w);
        }
        // stage B transposed: thread -> col n=t&63, k-range 8*(t>>6)..+7
        {
            int n  = t & 63;
            int q8 = (t >> 6) * 8;
            #pragma unroll
            for (int j = 0; j < 8; j++) {
                int k = q8 + j;
                sB[n][k] = f2tf32(W[(k0 + k) * HID + n0 + n]);
            }
        }
        __syncthreads();

        #pragma unroll
        for (int ks = 0; ks < KC; ks += 8) {
            unsigned a0 = sA[mw + g][ks + tig];
            unsigned a1 = sA[mw + g + 8][ks + tig];
            unsigned a2 = sA[mw + g][ks + tig + 4];
            unsigned a3 = sA[mw + g + 8][ks + tig + 4];
            #pragma unroll
            for (int s = 0; s < 4; s++) {
                unsigned b0 = sB[nw + s * 8 + g][ks + tig];
                unsigned b1 = sB[nw + s * 8 + g][ks + tig + 4];
                mma_tf32(c[s][0], c[s][1], c[s][2], c[s][3],
                         a0, a1, a2, a3, b0, b1);
            }
        }
        __syncthreads();
    }

    // Epilogue: c-reg layout: c0=(g, tig*2) c1=(g, tig*2+1) c2=(g+8, ...) c3.
    int head  = blockIdx.y * 2 + (w & 1);
    int node0 = m0 + mw + g;
    int node1 = node0 + 8;

    float2 as2[4], ad2[4];
    #pragma unroll
    for (int s = 0; s < 4; s++) {
        as2[s] = *(const float2*)&a_s[head * HDIM + s * 8 + tig * 2];
        ad2[s] = *(const float2*)&a_d[head * HDIM + s * 8 + tig * 2];
    }

    float ps0 = 0.f, pd0 = 0.f, ps1 = 0.f, pd1 = 0.f;
    #pragma unroll
    for (int s = 0; s < 4; s++) {
        int col = n0 + nw + s * 8 + tig * 2;
        if (node0 < N_NODES)
            *(__half2*)&g_h[node0 * HID + col] = __floats2half2_rn(c[s][0], c[s][1]);
        if (node1 < N_NODES)
            *(__half2*)&g_h[node1 * HID + col] = __floats2half2_rn(c[s][2], c[s][3]);
        ps0 += c[s][0] * as2[s].x + c[s][1] * as2[s].y;
        pd0 += c[s][0] * ad2[s].x + c[s][1] * ad2[s].y;
        ps1 += c[s][2] * as2[s].x + c[s][3] * as2[s].y;
        pd1 += c[s][2] * ad2[s].x + c[s][3] * ad2[s].y;
    }
    // reduce over tig (4 consecutive lanes)
    #pragma unroll
    for (int o = 2; o > 0; o >>= 1) {
        ps0 += __shfl_down_sync(0xffffffffu, ps0, o, 4);
        pd0 += __shfl_down_sync(0xffffffffu, pd0, o, 4);
        ps1 += __shfl_down_sync(0xffffffffu, ps1, o, 4);
        pd1 += __shfl_down_sync(0xffffffffu, pd1, o, 4);
    }
    if (tig == 0) {
        if (node0 < N_NODES) {
            g_as[node0 * HEADS + head] = ps0;
            g_ad[node0 * HEADS + head] = pd0;
        }
        if (node1 < N_NODES) {
            g_as[node1 * HEADS + head] = ps1;
            g_ad[node1 * HEADS + head] = pd1;
        }
    }
}

// ---------------- Aggregation: warp-per-node, zero smem, zero barriers ----------
// Grid: 1250 blocks x 256 threads; warp = node (n = blockIdx*8 + wid).
// Per edge: broadcast g_srt load; lane's head = lane>>2; lanes read the 32B
// g_as row and compute w = exp(leakyrelu(.)) inline. ALL lanes accumulate
// dsum += w -> every lane ends with its head's full denominator (quad lanes
// compute identical w), so no reduction of any kind is needed. Lane gathers
// uint4 = 8 fp16 channels (full 512B row per warp, one coalesced access).
// 2 edges in flight per trip. Fixed order -> deterministic.
// mode=1: out = elu(agg + b) -> g_feat ; mode=0: out = agg + b -> d_out
__global__ __launch_bounds__(256) void agg_kernel(
    const float* __restrict__ b, float* __restrict__ out, int mode)
{
    int t    = threadIdx.x;
    int wid  = t >> 5;
    int lane = t & 31;
    int hgrp = lane >> 2;               // head owning this lane's 8 channels

    int n = blockIdx.x * 8 + wid;       // 1250*8 = 10000 exactly

    int beg = g_off[n];
    int deg = g_off[n + 1] - beg;
    float adv = g_ad[n * HEADS + hgrp];

    float acc[8];
    #pragma unroll
    for (int i = 0; i < 8; i++) acc[i] = 0.f;
    float dsum = 0.f;

    int j = 0;
    for (; j + 1 < deg; j += 2) {
        int sa = g_srt[beg + j];
        int sb = g_srt[beg + j + 1];
        float ea = g_as[sa * HEADS + hgrp] + adv;
        float eb = g_as[sb * HEADS + hgrp] + adv;
        ea = (ea > 0.f) ? ea : 0.2f * ea;
        eb = (eb > 0.f) ? eb : 0.2f * eb;
        ea = fminf(fmaxf(ea, -60.f), 60.f);
        eb = fminf(fmaxf(eb, -60.f), 60.f);
        float wa = __expf(ea);
        float wb = __expf(eb);
        uint4 ha = ((const uint4*)g_h)[sa * (HID / 8) + lane];
        uint4 hb = ((const uint4*)g_h)[sb * (HID / 8) + lane];
        dsum += wa + wb;
        acc8(acc, ha, wa);
        acc8(acc, hb, wb);
    }
    if (j < deg) {
        int sa = g_srt[beg + j];
        float ea = g_as[sa * HEADS + hgrp] + adv;
        ea = (ea > 0.f) ? ea : 0.2f * ea;
        ea = fminf(fmaxf(ea, -60.f), 60.f);
        float wa = __expf(ea);
        uint4 ha = ((const uint4*)g_h)[sa * (HID / 8) + lane];
        dsum += wa;
        acc8(acc, ha, wa);
    }

    float inv = 1.f / (dsum + 1e-16f);
    float4 b0 = ((const float4*)b)[lane * 2];
    float4 b1 = ((const float4*)b)[lane * 2 + 1];
    float o0 = acc[0] * inv + b0.x;
    float o1 = acc[1] * inv + b0.y;
    float o2 = acc[2] * inv + b0.z;
    float o3 = acc[3] * inv + b0.w;
    float o4 = acc[4] * inv + b1.x;
    float o5 = acc[5] * inv + b1.y;
    float o6 = acc[6] * inv + b1.z;
    float o7 = acc[7] * inv + b1.w;
    if (mode == 1) {
        o0 = (o0 > 0.f) ? o0 : (__expf(o0) - 1.f);
        o1 = (o1 > 0.f) ? o1 : (__expf(o1) - 1.f);
        o2 = (o2 > 0.f) ? o2 : (__expf(o2) - 1.f);
        o3 = (o3 > 0.f) ? o3 : (__expf(o3) - 1.f);
        o4 = (o4 > 0.f) ? o4 : (__expf(o4) - 1.f);
        o5 = (o5 > 0.f) ? o5 : (__expf(o5) - 1.f);
        o6 = (o6 > 0.f) ? o6 : (__expf(o6) - 1.f);
        o7 = (o7 > 0.f) ? o7 : (__expf(o7) - 1.f);
        float4* dst = (float4*)&g_feat[n * HID + lane * 8];
        dst[0] = make_float4(o0, o1, o2, o3);
        dst[1] = make_float4(o4, o5, o6, o7);
    } else {
        float4* dst = (float4*)&out[n * HID + lane * 8];
        dst[0] = make_float4(o0, o1, o2, o3);
        dst[1] = make_float4(o4, o5, o6, o7);
    }
}

// ---------------- launch ----------------
extern "C" void kernel_launch(void* const* d_in, const int* in_sizes, int n_in,
                              void* d_out, int out_size)
{
    const float* x     = (const float*)d_in[0];
    const void*  edges = d_in[1];                 // int32 or int64 — detected on device
    const float* W1    = (const float*)d_in[2];
    const float* as1   = (const float*)d_in[3];
    const float* ad1   = (const float*)d_in[4];
    const float* b1    = (const float*)d_in[5];
    const float* W2    = (const float*)d_in[6];
    const float* as2   = (const float*)d_in[7];
    const float* ad2   = (const float*)d_in[8];
    const float* b2    = (const float*)d_in[9];
    float* out = (float*)d_out;

    // CSR build (deterministic)
    zero_detect_kernel<<<(DEG_PAD + 255) / 256, 256>>>((const int*)edges);
    hist_kernel<<<(N_EDGES / 4 + 255) / 256, 256>>>(edges);
    scan_kernel<<<1, 1024>>>();
    fill_kernel<<<(N_EDGES / 4 + 255) / 256, 256>>>(edges);

    dim3 ggrid((N_NODES + MB - 1) / MB, HID / NB);   // (157, 4)

    // Layer 1
    gemm_mma_kernel<<<ggrid, 256>>>(x, 0, W1, as1, ad1);
    agg_kernel<<<N_NODES / 8, 256>>>(b1, out, /*mode=*/1);

    // Layer 2
    gemm_mma_kernel<<<ggrid, 256>>>(x, 1, W2, as2, ad2);
    agg_kernel<<<N_NODES / 8, 256>>>(b2, out, /*mode=*/0);
}

// round 17
// speedup vs baseline: 2.4081x; 1.0162x over previous
#include <cuda_runtime.h>
#include <cuda_fp16.h>
#include <math_constants.h>

#define N_NODES 10000
#define N_EDGES 320000
#define HID 256
#define HEADS 8
#define HDIM 32
#define DEG_PAD 12288  // 1024 threads * 12 per thread, int4-aligned

// GEMM tiling
#define MB 64
#define NB 64
#define KC 32
#define KPAD 36        // row pad (floats) -> conflict-free mma fragment LDS

// ---------------- scratch (no allocation allowed) ----------------
__device__ __half g_h[N_NODES * HID];    // transformed features (fp16 messages)
__device__ float g_feat[N_NODES * HID];  // layer-2 input (elu(out1)), fp32
__device__ float g_as[N_NODES * HEADS];
__device__ float g_ad[N_NODES * HEADS];
__device__ int   g_deg[DEG_PAD];         // zero-initialized at load; fill re-zeroes for next call
__device__ int   g_off[N_NODES + 1];
__device__ int   g_rank[N_EDGES];        // rank of edge within its dst bucket
__device__ int   g_srt[N_EDGES];         // src node id, grouped by dst (CSR)
__device__ int   g_is64;                 // 1 if edges buffer is int64, 0 if int32

// ---------------- helpers ----------------
__device__ __forceinline__ int edge_at(const void* edges, int idx) {
    if (g_is64) return (int)((const long long*)edges)[idx];
    return ((const int*)edges)[idx];
}

__device__ __forceinline__ unsigned f2tf32(float f) {
    unsigned u;
    asm("cvt.rna.tf32.f32 %0, %1;" : "=r"(u) : "f"(f));
    return u;
}

__device__ __forceinline__ void mma_tf32(
    float& c0, float& c1, float& c2, float& c3,
    unsigned a0, unsigned a1, unsigned a2, unsigned a3,
    unsigned b0, unsigned b1)
{
    asm("mma.sync.aligned.m16n8k8.row.col.f32.tf32.tf32.f32 "
        "{%0,%1,%2,%3},{%4,%5,%6,%7},{%8,%9},{%0,%1,%2,%3};"
        : "+f"(c0), "+f"(c1), "+f"(c2), "+f"(c3)
        : "r"(a0), "r"(a1), "r"(a2), "r"(a3), "r"(b0), "r"(b1));
}

__device__ __forceinline__ void acc8(float* acc, uint4 hv, float w) {
    float2 f;
    f = __half22float2(*(__half2*)&hv.x);
    acc[0] = fmaf(f.x, w, acc[0]); acc[1] = fmaf(f.y, w, acc[1]);
    f = __half22float2(*(__half2*)&hv.y);
    acc[2] = fmaf(f.x, w, acc[2]); acc[3] = fmaf(f.y, w, acc[3]);
    f = __half22float2(*(__half2*)&hv.z);
    acc[4] = fmaf(f.x, w, acc[4]); acc[5] = fmaf(f.y, w, acc[5]);
    f = __half22float2(*(__half2*)&hv.w);
    acc[6] = fmaf(f.x, w, acc[6]); acc[7] = fmaf(f.y, w, acc[7]);
}

// ---------------- dtype detect: 32 threads, one parallel load + ballot ----------
__global__ void detect_kernel(const int* __restrict__ e32) {
    int odd = e32[threadIdx.x * 2 + 1];
    unsigned m = __ballot_sync(0xffffffffu, odd != 0);
    if (threadIdx.x == 0) g_is64 = (m == 0) ? 1 : 0;
}

// ---------------- histogram: 4 edges per thread, COALESCED (lanes consecutive) --
__global__ void hist_kernel(const void* __restrict__ edges) {
    int base = blockIdx.x * 1024 + threadIdx.x;
    #pragma unroll
    for (int k = 0; k < 4; k++) {
        int e = base + k * 256;
        if (e < N_EDGES) {
            int dst = edge_at(edges, N_EDGES + e);
            int r = 0;
            if ((unsigned)dst < (unsigned)N_NODES)
                r = atomicAdd(&g_deg[dst], 1);
            g_rank[e] = r;
        }
    }
}

// Two-level warp-shuffle scan; thread t serially scans 12 elems (3x int4 loads).
__global__ __launch_bounds__(1024) void scan_kernel() {
    __shared__ int warp_tot[32];
    const int PER = 12;
    int t    = threadIdx.x;
    int lane = t & 31, wid = t >> 5;

    int d[PER];
    #pragma unroll
    for (int q = 0; q < 3; q++) {
        int4 v4 = ((const int4*)g_deg)[t * 3 + q];
        d[q * 4 + 0] = v4.x; d[q * 4 + 1] = v4.y;
        d[q * 4 + 2] = v4.z; d[q * 4 + 3] = v4.w;
    }
    int v[PER]; int s = 0;
    #pragma unroll
    for (int i = 0; i < PER; i++) { v[i] = s; s += d[i]; }

    int x = s;
    #pragma unroll
    for (int o = 1; o < 32; o <<= 1) {
        int y = __shfl_up_sync(0xffffffffu, x, o);
        if (lane >= o) x += y;
    }
    if (lane == 31) warp_tot[wid] = x;
    __syncthreads();
    if (wid == 0) {
        int y = warp_tot[lane];
        #pragma unroll
        for (int o = 1; o < 32; o <<= 1) {
            int z = __shfl_up_sync(0xffffffffu, y, o);
            if (lane >= o) y += z;
        }
        warp_tot[lane] = y;
    }
    __syncthreads();
    int excl = x - s + (wid > 0 ? warp_tot[wid - 1] : 0);
    int base = t * PER;
    #pragma unroll
    for (int i = 0; i < PER; i++) {
        int idx = base + i;
        if (idx <= N_NODES) g_off[idx] = excl + v[i];  // padding degs are 0
    }
}

// atomic-free fill (precomputed ranks), coalesced 4-way; also re-zeroes g_deg
// for the NEXT call (nothing reads g_deg after scan within this call).
__global__ void fill_kernel(const void* __restrict__ edges) {
    int tid  = blockIdx.x * blockDim.x + threadIdx.x;
    int base = blockIdx.x * 1024 + threadIdx.x;
    #pragma unroll
    for (int k = 0; k < 4; k++) {
        int e = base + k * 256;
        if (e < N_EDGES) {
            int src = edge_at(edges, e);
            int dst = edge_at(edges, N_EDGES + e);
            if ((unsigned)src < (unsigned)N_NODES && (unsigned)dst < (unsigned)N_NODES) {
                int pos = g_off[dst] + g_rank[e];
                if ((unsigned)pos < (unsigned)N_EDGES) g_srt[pos] = src;
            }
        }
    }
    if (tid < DEG_PAD) g_deg[tid] = 0;
}

// ---------------- GEMM (tf32 tensor cores): h = feat @ W + fused alphas ---------
// Block 256 thr = 8 warps; block tile 64 nodes x 64 cols; warp tile 16x32.
// Warp grid 4(m) x 2(n): warp w -> mw=(w>>1)*16, nw=(w&1)*32 (= exactly one head).
// h stored as fp16 (half2 pairs); alpha dots from fp32 accumulators.
__global__ __launch_bounds__(256) void gemm_mma_kernel(
    const float* __restrict__ x, int layer2, const float* __restrict__ W,
    const float* __restrict__ a_s, const float* __restrict__ a_d)
{
    const float* feat = layer2 ? (const float*)g_feat : x;

    __shared__ unsigned sA[MB][KPAD];   // A tile [row][k] (tf32 bits)
    __shared__ unsigned sB[NB][KPAD];   // B tile [col][k] (tf32 bits)

    int t    = threadIdx.x;
    int w    = t >> 5;
    int lane = t & 31;
    int g    = lane >> 2;     // 0..7
    int tig  = lane & 3;      // 0..3
    int m0 = blockIdx.x * MB;
    int n0 = blockIdx.y * NB;
    int mw = (w >> 1) * 16;
    int nw = (w & 1) * 32;

    float c[4][4];
    #pragma unroll
    for (int s = 0; s < 4; s++)
        #pragma unroll
        for (int i = 0; i < 4; i++) c[s][i] = 0.f;

    for (int k0 = 0; k0 < HID; k0 += KC) {
        // stage A: 64 rows x 32 k, float4 loads along k
        #pragma unroll
        for (int q = 0; q < 2; q++) {
            int lin = t + 256 * q;          // 0..511
            int row = lin >> 3;
            int kq  = (lin & 7) * 4;
            int node = m0 + row;
            float4 v = (node < N_NODES)
                ? *(const float4*)&feat[node * HID + k0 + kq]
                : make_float4(0.f, 0.f, 0.f, 0.f);
            sA[row][kq + 0] = f2tf32(v.x);
            sA[row][kq + 1] = f2tf32(v.y);
            sA[row][kq + 2] = f2tf32(v.z);
            sA[row][kq + 3] = f2tf32(v.w);
        }
        // stage B transposed: thread -> col n=t&63, k-range 8*(t>>6)..+7
        {
            int n  = t & 63;
            int q8 = (t >> 6) * 8;
            #pragma unroll
            for (int j = 0; j < 8; j++) {
                int k = q8 + j;
                sB[n][k] = f2tf32(W[(k0 + k) * HID + n0 + n]);
            }
        }
        __syncthreads();

        #pragma unroll
        for (int ks = 0; ks < KC; ks += 8) {
            unsigned a0 = sA[mw + g][ks + tig];
            unsigned a1 = sA[mw + g + 8][ks + tig];
            unsigned a2 = sA[mw + g][ks + tig + 4];
            unsigned a3 = sA[mw + g + 8][ks + tig + 4];
            #pragma unroll
            for (int s = 0; s < 4; s++) {
                unsigned b0 = sB[nw + s * 8 + g][ks + tig];
                unsigned b1 = sB[nw + s * 8 + g][ks + tig + 4];
                mma_tf32(c[s][0], c[s][1], c[s][2], c[s][3],
                         a0, a1, a2, a3, b0, b1);
            }
        }
        __syncthreads();
    }

    // Epilogue: c-reg layout: c0=(g, tig*2) c1=(g, tig*2+1) c2=(g+8, ...) c3.
    int head  = blockIdx.y * 2 + (w & 1);
    int node0 = m0 + mw + g;
    int node1 = node0 + 8;

    float2 as2[4], ad2[4];
    #pragma unroll
    for (int s = 0; s < 4; s++) {
        as2[s] = *(const float2*)&a_s[head * HDIM + s * 8 + tig * 2];
        ad2[s] = *(const float2*)&a_d[head * HDIM + s * 8 + tig * 2];
    }

    float ps0 = 0.f, pd0 = 0.f, ps1 = 0.f, pd1 = 0.f;
    #pragma unroll
    for (int s = 0; s < 4; s++) {
        int col = n0 + nw + s * 8 + tig * 2;
        if (node0 < N_NODES)
            *(__half2*)&g_h[node0 * HID + col] = __floats2half2_rn(c[s][0], c[s][1]);
        if (node1 < N_NODES)
            *(__half2*)&g_h[node1 * HID + col] = __floats2half2_rn(c[s][2], c[s][3]);
        ps0 += c[s][0] * as2[s].x + c[s][1] * as2[s].y;
        pd0 += c[s][0] * ad2[s].x + c[s][1] * ad2[s].y;
        ps1 += c[s][2] * as2[s].x + c[s][3] * as2[s].y;
        pd1 += c[s][2] * ad2[s].x + c[s][3] * ad2[s].y;
    }
    // reduce over tig (4 consecutive lanes)
    #pragma unroll
    for (int o = 2; o > 0; o >>= 1) {
        ps0 += __shfl_down_sync(0xffffffffu, ps0, o, 4);
        pd0 += __shfl_down_sync(0xffffffffu, pd0, o, 4);
        ps1 += __shfl_down_sync(0xffffffffu, ps1, o, 4);
        pd1 += __shfl_down_sync(0xffffffffu, pd1, o, 4);
    }
    if (tig == 0) {
        if (node0 < N_NODES) {
            g_as[node0 * HEADS + head] = ps0;
            g_ad[node0 * HEADS + head] = pd0;
        }
        if (node1 < N_NODES) {
            g_as[node1 * HEADS + head] = ps1;
            g_ad[node1 * HEADS + head] = pd1;
        }
    }
}

// ---------------- Aggregation: warp-per-node, zero smem, zero barriers ----------
// Grid: 1250 blocks x 256 threads; warp = node (n = blockIdx*8 + wid).
// Per edge: broadcast g_srt load; lane's head = lane>>2; lanes read the 32B
// g_as row and compute w = exp(leakyrelu(.)) inline. ALL lanes accumulate
// dsum += w -> every lane ends with its head's full denominator (quad lanes
// compute identical w), so no reduction of any kind is needed. Lane gathers
// uint4 = 8 fp16 channels (full 512B row per warp, one coalesced access).
// 2 edges in flight per trip. Fixed order -> deterministic.
// mode=1: out = elu(agg + b) -> g_feat ; mode=0: out = agg + b -> d_out
__global__ __launch_bounds__(256) void agg_kernel(
    const float* __restrict__ b, float* __restrict__ out, int mode)
{
    int t    = threadIdx.x;
    int wid  = t >> 5;
    int lane = t & 31;
    int hgrp = lane >> 2;               // head owning this lane's 8 channels

    int n = blockIdx.x * 8 + wid;       // 1250*8 = 10000 exactly

    int beg = g_off[n];
    int deg = g_off[n + 1] - beg;
    float adv = g_ad[n * HEADS + hgrp];

    float acc[8];
    #pragma unroll
    for (int i = 0; i < 8; i++) acc[i] = 0.f;
    float dsum = 0.f;

    int j = 0;
    for (; j + 1 < deg; j += 2) {
        int sa = g_srt[beg + j];
        int sb = g_srt[beg + j + 1];
        float ea = g_as[sa * HEADS + hgrp] + adv;
        float eb = g_as[sb * HEADS + hgrp] + adv;
        ea = (ea > 0.f) ? ea : 0.2f * ea;
        eb = (eb > 0.f) ? eb : 0.2f * eb;
        ea = fminf(fmaxf(ea, -60.f), 60.f);
        eb = fminf(fmaxf(eb, -60.f), 60.f);
        float wa = __expf(ea);
        float wb = __expf(eb);
        uint4 ha = ((const uint4*)g_h)[sa * (HID / 8) + lane];
        uint4 hb = ((const uint4*)g_h)[sb * (HID / 8) + lane];
        dsum += wa + wb;
        acc8(acc, ha, wa);
        acc8(acc, hb, wb);
    }
    if (j < deg) {
        int sa = g_srt[beg + j];
        float ea = g_as[sa * HEADS + hgrp] + adv;
        ea = (ea > 0.f) ? ea : 0.2f * ea;
        ea = fminf(fmaxf(ea, -60.f), 60.f);
        float wa = __expf(ea);
        uint4 ha = ((const uint4*)g_h)[sa * (HID / 8) + lane];
        dsum += wa;
        acc8(acc, ha, wa);
    }

    float inv = 1.f / (dsum + 1e-16f);
    float4 b0 = ((const float4*)b)[lane * 2];
    float4 b1 = ((const float4*)b)[lane * 2 + 1];
    float o0 = acc[0] * inv + b0.x;
    float o1 = acc[1] * inv + b0.y;
    float o2 = acc[2] * inv + b0.z;
    float o3 = acc[3] * inv + b0.w;
    float o4 = acc[4] * inv + b1.x;
    float o5 = acc[5] * inv + b1.y;
    float o6 = acc[6] * inv + b1.z;
    float o7 = acc[7] * inv + b1.w;
    if (mode == 1) {
        o0 = (o0 > 0.f) ? o0 : (__expf(o0) - 1.f);
        o1 = (o1 > 0.f) ? o1 : (__expf(o1) - 1.f);
        o2 = (o2 > 0.f) ? o2 : (__expf(o2) - 1.f);
        o3 = (o3 > 0.f) ? o3 : (__expf(o3) - 1.f);
        o4 = (o4 > 0.f) ? o4 : (__expf(o4) - 1.f);
        o5 = (o5 > 0.f) ? o5 : (__expf(o5) - 1.f);
        o6 = (o6 > 0.f) ? o6 : (__expf(o6) - 1.f);
        o7 = (o7 > 0.f) ? o7 : (__expf(o7) - 1.f);
        float4* dst = (float4*)&g_feat[n * HID + lane * 8];
        dst[0] = make_float4(o0, o1, o2, o3);
        dst[1] = make_float4(o4, o5, o6, o7);
    } else {
        float4* dst = (float4*)&out[n * HID + lane * 8];
        dst[0] = make_float4(o0, o1, o2, o3);
        dst[1] = make_float4(o4, o5, o6, o7);
    }
}

// ---------------- launch ----------------
extern "C" void kernel_launch(void* const* d_in, const int* in_sizes, int n_in,
                              void* d_out, int out_size)
{
    const float* x     = (const float*)d_in[0];
    const void*  edges = d_in[1];                 // int32 or int64 — detected on device
    const float* W1    = (const float*)d_in[2];
    const float* as1   = (const float*)d_in[3];
    const float* ad1   = (const float*)d_in[4];
    const float* b1    = (const float*)d_in[5];
    const float* W2    = (const float*)d_in[6];
    const float* as2   = (const float*)d_in[7];
    const float* ad2   = (const float*)d_in[8];
    const float* b2    = (const float*)d_in[9];
    float* out = (float*)d_out;

    // CSR build (deterministic; g_deg enters zeroed — static init on first call,
    // re-zeroed by fill_kernel on every call thereafter)
    detect_kernel<<<1, 32>>>((const int*)edges);
    hist_kernel<<<(N_EDGES + 1023) / 1024, 256>>>(edges);
    scan_kernel<<<1, 1024>>>();
    fill_kernel<<<(N_EDGES + 1023) / 1024, 256>>>(edges);

    dim3 ggrid((N_NODES + MB - 1) / MB, HID / NB);   // (157, 4)

    // Layer 1
    gemm_mma_kernel<<<ggrid, 256>>>(x, 0, W1, as1, ad1);
    agg_kernel<<<N_NODES / 8, 256>>>(b1, out, /*mode=*/1);

    // Layer 2
    gemm_mma_kernel<<<ggrid, 256>>>(x, 1, W2, as2, ad2);
    agg_kernel<<<N_NODES / 8, 256>>>(b2, out, /*mode=*/0);
}